// round 1
// baseline (speedup 1.0000x reference)
#include <cuda_runtime.h>
#include <cuda_bf16.h>
#include <cstdint>

#define T_LEN 2048
#define D_MODEL 1024
#define H_NUM 16
#define HS 64
#define CHUNK 128
#define NC (T_LEN / CHUNK)   /* 16 */
#define EPSF 1e-6f

// ---------------- scratch (static device globals; no allocation) ----------------
__device__ float g_qkv[T_LEN * 3 * D_MODEL];          // [T, 3, H, Hs]
__device__ float g_xo [T_LEN * D_MODEL];              // [T, D] (heads concat)
__device__ float g_Sc [H_NUM * NC * HS * HS];         // per-chunk KV sums
__device__ float g_Sp [H_NUM * NC * HS * HS];         // exclusive prefix of Sc
__device__ float g_zc [H_NUM * NC * HS];              // per-chunk k sums
__device__ float g_zp [H_NUM * NC * HS];              // exclusive prefix of zc

__device__ __forceinline__ float phi(float x) {
    // elu(x) + 1 : x>=0 -> x+1 ; x<0 -> exp(x)
    return x > 0.f ? x + 1.f : expf(x);
}

// ---------------- SGEMM: C[M][N] = A[M][K] @ B[N][K]^T (both row-major, K-contig) ----
__global__ __launch_bounds__(256) void sgemm_nt(const float* __restrict__ A,
                                                const float* __restrict__ B,
                                                float* __restrict__ C,
                                                int M, int N, int K) {
    __shared__ float As[16][128];
    __shared__ float Bs[16][128];
    int tid = threadIdx.x;
    int ty = tid >> 4, tx = tid & 15;
    int m0 = blockIdx.y * 128, n0 = blockIdx.x * 128;

    float acc[8][8];
#pragma unroll
    for (int i = 0; i < 8; i++)
#pragma unroll
        for (int j = 0; j < 8; j++) acc[i][j] = 0.f;

    for (int k0 = 0; k0 < K; k0 += 16) {
#pragma unroll
        for (int l = 0; l < 2; l++) {
            int f4  = tid + l * 256;
            int row = f4 >> 2;            // 0..127
            int kk  = (f4 & 3) << 2;      // 0,4,8,12
            float4 va = *(const float4*)(A + (size_t)(m0 + row) * K + k0 + kk);
            As[kk + 0][row] = va.x; As[kk + 1][row] = va.y;
            As[kk + 2][row] = va.z; As[kk + 3][row] = va.w;
            float4 vb = *(const float4*)(B + (size_t)(n0 + row) * K + k0 + kk);
            Bs[kk + 0][row] = vb.x; Bs[kk + 1][row] = vb.y;
            Bs[kk + 2][row] = vb.z; Bs[kk + 3][row] = vb.w;
        }
        __syncthreads();
#pragma unroll
        for (int kk = 0; kk < 16; kk++) {
            float af[8], bf[8];
            *(float4*)(af)     = *(const float4*)&As[kk][ty * 8];
            *(float4*)(af + 4) = *(const float4*)&As[kk][ty * 8 + 4];
            *(float4*)(bf)     = *(const float4*)&Bs[kk][tx * 8];
            *(float4*)(bf + 4) = *(const float4*)&Bs[kk][tx * 8 + 4];
#pragma unroll
            for (int i = 0; i < 8; i++)
#pragma unroll
                for (int j = 0; j < 8; j++)
                    acc[i][j] = fmaf(af[i], bf[j], acc[i][j]);
        }
        __syncthreads();
    }

#pragma unroll
    for (int i = 0; i < 8; i++) {
        float* crow = C + (size_t)(m0 + ty * 8 + i) * N + n0 + tx * 8;
        *(float4*)(crow)     = make_float4(acc[i][0], acc[i][1], acc[i][2], acc[i][3]);
        *(float4*)(crow + 4) = make_float4(acc[i][4], acc[i][5], acc[i][6], acc[i][7]);
    }
}

// ---------------- per-chunk KV sums: Sc[h,c] = sum_t phi(k_t) v_t^T ; zc = sum_t phi(k_t)
__global__ __launch_bounds__(256) void chunk_sums() {
    extern __shared__ float sm[];
    float* Ks = sm;                 // [CHUNK][HS]
    float* Vs = sm + CHUNK * HS;    // [CHUNK][HS]
    int blk = blockIdx.x;
    int h = blk >> 4, c = blk & 15;
    int t0 = c * CHUNK;
    int tid = threadIdx.x;

    for (int i = tid; i < CHUNK * HS; i += 256) {
        int t = i >> 6, d = i & 63;
        const float* base = g_qkv + (size_t)(t0 + t) * (3 * D_MODEL) + h * HS + d;
        Ks[i] = phi(base[D_MODEL]);
        Vs[i] = base[2 * D_MODEL];
    }
    __syncthreads();

    int d0 = (tid >> 4) * 4, f0 = (tid & 15) * 4;
    float acc[4][4];
#pragma unroll
    for (int i = 0; i < 4; i++)
#pragma unroll
        for (int j = 0; j < 4; j++) acc[i][j] = 0.f;

    for (int t = 0; t < CHUNK; t++) {
        float4 k4 = *(const float4*)&Ks[t * HS + d0];
        float4 v4 = *(const float4*)&Vs[t * HS + f0];
        float kf[4] = {k4.x, k4.y, k4.z, k4.w};
        float vf[4] = {v4.x, v4.y, v4.z, v4.w};
#pragma unroll
        for (int i = 0; i < 4; i++)
#pragma unroll
            for (int j = 0; j < 4; j++)
                acc[i][j] = fmaf(kf[i], vf[j], acc[i][j]);
    }
    float* Sout = g_Sc + (size_t)blk * HS * HS;
#pragma unroll
    for (int i = 0; i < 4; i++)
#pragma unroll
        for (int j = 0; j < 4; j++)
            Sout[(d0 + i) * HS + f0 + j] = acc[i][j];

    if (tid < HS) {
        float z = 0.f;
        for (int t = 0; t < CHUNK; t++) z += Ks[t * HS + tid];
        g_zc[blk * HS + tid] = z;
    }
}

// ---------------- exclusive prefix over chunks, per head ----------------
__global__ __launch_bounds__(256) void chunk_prefix() {
    int h = blockIdx.x;
    for (int i = threadIdx.x; i < HS * HS; i += 256) {
        float run = 0.f;
#pragma unroll
        for (int c = 0; c < NC; c++) {
            size_t idx = (size_t)(h * NC + c) * HS * HS + i;
            g_Sp[idx] = run;
            run += g_Sc[idx];
        }
    }
    if (threadIdx.x < HS) {
        float run = 0.f;
#pragma unroll
        for (int c = 0; c < NC; c++) {
            int idx = (h * NC + c) * HS + threadIdx.x;
            g_zp[idx] = run;
            run += g_zc[idx];
        }
    }
}

// ---------------- per-chunk output ----------------
// O[t] = ( Q[t]·Sp + sum_{s<=t} (Q[t]·K[s]) V[s] ) / ( Q[t]·zp + rowsum(masked A) + eps )
#define QP 136   // pitch for d-major Q/K tiles
#define VP 68    // pitch for t-major V / Sp tiles
#define AP 132   // pitch for A[t][s]
__global__ __launch_bounds__(256) void attn_out() {
    extern __shared__ float sm[];
    float* Qt  = sm;                   // [HS][QP]   Qt[d*QP + t] = phi(q)
    float* Kt  = Qt + HS * QP;         // [HS][QP]
    float* Vs  = Kt + HS * QP;         // [CHUNK][VP]
    float* Am  = Vs + CHUNK * VP;      // [CHUNK][AP]  A[t][s]
    float* Sps = Am + CHUNK * AP;      // [HS][VP]
    float* zps = Sps + HS * VP;        // [HS]
    float* den = zps + HS;             // [CHUNK]

    int blk = blockIdx.x;
    int h = blk >> 4, c = blk & 15;
    int t0g = c * CHUNK;
    int tid = threadIdx.x;

    for (int i = tid; i < CHUNK * HS; i += 256) {
        int t = i >> 6, d = i & 63;
        const float* base = g_qkv + (size_t)(t0g + t) * (3 * D_MODEL) + h * HS + d;
        Qt[d * QP + t] = phi(base[0]);
        Kt[d * QP + t] = phi(base[D_MODEL]);
        Vs[t * VP + d] = base[2 * D_MODEL];
    }
    const float* SpG = g_Sp + (size_t)blk * HS * HS;
    for (int i = tid; i < HS * HS; i += 256)
        Sps[(i >> 6) * VP + (i & 63)] = SpG[i];
    if (tid < HS) zps[tid] = g_zp[blk * HS + tid];
    __syncthreads();

    // Step 1: A = Q K^T, causal-masked, row-major into Am
    {
        int ty = tid >> 4, tx = tid & 15;
        int tt0 = ty * 8, ss0 = tx * 8;
        float acc[8][8];
#pragma unroll
        for (int i = 0; i < 8; i++)
#pragma unroll
            for (int j = 0; j < 8; j++) acc[i][j] = 0.f;

        for (int d = 0; d < HS; d++) {
            float qf[8], kf[8];
            *(float4*)(qf)     = *(const float4*)&Qt[d * QP + tt0];
            *(float4*)(qf + 4) = *(const float4*)&Qt[d * QP + tt0 + 4];
            *(float4*)(kf)     = *(const float4*)&Kt[d * QP + ss0];
            *(float4*)(kf + 4) = *(const float4*)&Kt[d * QP + ss0 + 4];
#pragma unroll
            for (int i = 0; i < 8; i++)
#pragma unroll
                for (int j = 0; j < 8; j++)
                    acc[i][j] = fmaf(qf[i], kf[j], acc[i][j]);
        }
#pragma unroll
        for (int i = 0; i < 8; i++) {
            int t = tt0 + i;
            float w[8];
#pragma unroll
            for (int j = 0; j < 8; j++)
                w[j] = (ss0 + j <= t) ? acc[i][j] : 0.f;
            *(float4*)&Am[t * AP + ss0]     = make_float4(w[0], w[1], w[2], w[3]);
            *(float4*)&Am[t * AP + ss0 + 4] = make_float4(w[4], w[5], w[6], w[7]);
        }
    }
    __syncthreads();

    // Step 2: denominators
    if (tid < CHUNK) {
        int t = tid;
        float s = 0.f;
        for (int ss = 0; ss < CHUNK; ss++) s += Am[t * AP + ss];
        float qz = 0.f;
        for (int d = 0; d < HS; d++) qz = fmaf(Qt[d * QP + t], zps[d], qz);
        den[t] = s + qz + EPSF;
    }
    __syncthreads();

    // Step 3: O = A V + Q Sp, divide, write
    {
        int ty = tid >> 4, tx = tid & 15;
        int tt0 = ty * 8, f0 = tx * 4;
        float acc[8][4];
#pragma unroll
        for (int i = 0; i < 8; i++)
#pragma unroll
            for (int j = 0; j < 4; j++) acc[i][j] = 0.f;

        for (int s = 0; s < CHUNK; s++) {
            float4 v4 = *(const float4*)&Vs[s * VP + f0];
            float vf[4] = {v4.x, v4.y, v4.z, v4.w};
#pragma unroll
            for (int i = 0; i < 8; i++) {
                float a = Am[(tt0 + i) * AP + s];
#pragma unroll
                for (int j = 0; j < 4; j++)
                    acc[i][j] = fmaf(a, vf[j], acc[i][j]);
            }
        }
        for (int d = 0; d < HS; d++) {
            float4 sp4 = *(const float4*)&Sps[d * VP + f0];
            float spf[4] = {sp4.x, sp4.y, sp4.z, sp4.w};
            float qf[8];
            *(float4*)(qf)     = *(const float4*)&Qt[d * QP + tt0];
            *(float4*)(qf + 4) = *(const float4*)&Qt[d * QP + tt0 + 4];
#pragma unroll
            for (int i = 0; i < 8; i++)
#pragma unroll
                for (int j = 0; j < 4; j++)
                    acc[i][j] = fmaf(qf[i], spf[j], acc[i][j]);
        }
#pragma unroll
        for (int i = 0; i < 8; i++) {
            int t = tt0 + i;
            float inv = 1.f / den[t];
            float* dst = g_xo + (size_t)(t0g + t) * D_MODEL + h * HS + f0;
            *(float4*)dst = make_float4(acc[i][0] * inv, acc[i][1] * inv,
                                        acc[i][2] * inv, acc[i][3] * inv);
        }
    }
}

// ---------------- launch ----------------
extern "C" void kernel_launch(void* const* d_in, const int* in_sizes, int n_in,
                              void* d_out, int out_size) {
    const float* x     = (const float*)d_in[0];
    const float* w_qkv = (const float*)d_in[1];
    const float* w_out = (const float*)d_in[2];
    float* out = (float*)d_out;

    float *qkv, *xo;
    cudaGetSymbolAddress((void**)&qkv, g_qkv);
    cudaGetSymbolAddress((void**)&xo,  g_xo);

    const int CHUNK_SMEM = 2 * CHUNK * HS * sizeof(float);           // 64 KB
    const int ATTN_SMEM  = (HS * QP * 2 + CHUNK * VP + CHUNK * AP +
                            HS * VP + HS + CHUNK) * sizeof(float);    // ~190 KB
    cudaFuncSetAttribute(chunk_sums, cudaFuncAttributeMaxDynamicSharedMemorySize, CHUNK_SMEM);
    cudaFuncSetAttribute(attn_out,   cudaFuncAttributeMaxDynamicSharedMemorySize, ATTN_SMEM);

    dim3 g1(3 * D_MODEL / 128, T_LEN / 128);   // (24, 16)
    sgemm_nt<<<g1, 256>>>(x, w_qkv, qkv, T_LEN, 3 * D_MODEL, D_MODEL);

    chunk_sums<<<H_NUM * NC, 256, CHUNK_SMEM>>>();
    chunk_prefix<<<H_NUM, 256>>>();
    attn_out<<<H_NUM * NC, 256, ATTN_SMEM>>>();

    dim3 g2(D_MODEL / 128, T_LEN / 128);       // (8, 16)
    sgemm_nt<<<g2, 256>>>(xo, w_out, out, T_LEN, D_MODEL, D_MODEL);
}

// round 3
// speedup vs baseline: 1.9542x; 1.9542x over previous
#include <cuda_runtime.h>
#include <cuda_bf16.h>
#include <cstdint>

#define T_LEN 2048
#define D_MODEL 1024
#define H_NUM 16
#define HS 64
#define CHUNK 128
#define NC (T_LEN / CHUNK)   /* 16 */
#define EPSF 1e-6f

// ---------------- scratch (static device globals; no allocation) ----------------
__device__ float g_qkv[T_LEN * 3 * D_MODEL];          // [T, 3, H, Hs]
__device__ float g_xo [T_LEN * D_MODEL];              // [T, D]
__device__ float g_Sc [H_NUM * NC * HS * HS];
__device__ float g_Sp [H_NUM * NC * HS * HS];
__device__ float g_zc [H_NUM * NC * HS];
__device__ float g_zp [H_NUM * NC * HS];

// bf16 split copies (hi/lo)
__device__ __align__(16) __nv_bfloat16 g_ah [T_LEN * D_MODEL];       // A hi (x / xo)
__device__ __align__(16) __nv_bfloat16 g_al [T_LEN * D_MODEL];       // A lo
__device__ __align__(16) __nv_bfloat16 g_b1h[3 * D_MODEL * D_MODEL]; // w_qkv hi
__device__ __align__(16) __nv_bfloat16 g_b1l[3 * D_MODEL * D_MODEL]; // w_qkv lo
__device__ __align__(16) __nv_bfloat16 g_b2h[D_MODEL * D_MODEL];     // w_out hi
__device__ __align__(16) __nv_bfloat16 g_b2l[D_MODEL * D_MODEL];     // w_out lo

__device__ __forceinline__ float phi(float x) {
    return x > 0.f ? x + 1.f : expf(x);
}

// ============================================================================
// fp32 -> bf16 (hi, lo) split, vectorized by 4
// ============================================================================
__global__ __launch_bounds__(256) void splitk(const float* __restrict__ s,
                                              __nv_bfloat16* __restrict__ h,
                                              __nv_bfloat16* __restrict__ l,
                                              int n4) {
    int i = blockIdx.x * 256 + threadIdx.x;
    if (i >= n4) return;
    float4 v = ((const float4*)s)[i];
    float f[4] = {v.x, v.y, v.z, v.w};
    uint32_t hw[4], lw[4];
#pragma unroll
    for (int j = 0; j < 4; j++) {
        __nv_bfloat16 hb = __float2bfloat16_rn(f[j]);
        float r = f[j] - __bfloat162float(hb);
        __nv_bfloat16 lb = __float2bfloat16_rn(r);
        hw[j] = (uint32_t)__bfloat16_as_ushort(hb);
        lw[j] = (uint32_t)__bfloat16_as_ushort(lb);
    }
    ((uint2*)h)[i] = make_uint2(hw[0] | (hw[1] << 16), hw[2] | (hw[3] << 16));
    ((uint2*)l)[i] = make_uint2(lw[0] | (lw[1] << 16), lw[2] | (lw[3] << 16));
}

// ============================================================================
// mma.sync helpers
// ============================================================================
__device__ __forceinline__ uint32_t smem_u32(const void* p) {
    uint32_t a;
    asm("{ .reg .u64 t; cvta.to.shared.u64 t, %1; cvt.u32.u64 %0, t; }" : "=r"(a) : "l"(p));
    return a;
}
__device__ __forceinline__ void ldsm4(uint32_t* r, uint32_t addr) {
    asm volatile("ldmatrix.sync.aligned.m8n8.x4.shared.b16 {%0,%1,%2,%3}, [%4];"
                 : "=r"(r[0]), "=r"(r[1]), "=r"(r[2]), "=r"(r[3]) : "r"(addr));
}
__device__ __forceinline__ void mma16816(float* d, const uint32_t* a, const uint32_t* b) {
    asm volatile("mma.sync.aligned.m16n8k16.row.col.f32.bf16.bf16.f32 "
                 "{%0,%1,%2,%3},{%4,%5,%6,%7},{%8,%9},{%0,%1,%2,%3};"
                 : "+f"(d[0]), "+f"(d[1]), "+f"(d[2]), "+f"(d[3])
                 : "r"(a[0]), "r"(a[1]), "r"(a[2]), "r"(a[3]), "r"(b[0]), "r"(b[1]));
}
#define CP16(dst, src) \
    asm volatile("cp.async.cg.shared.global [%0], [%1], 16;" :: "r"(dst), "l"(src) : "memory")
#define CP_COMMIT() asm volatile("cp.async.commit_group;" ::: "memory")
#define CP_WAIT0()  asm volatile("cp.async.wait_group 0;" ::: "memory")

// ============================================================================
// split-bf16 GEMM: C[M][N] = A[M][K] @ B[N][K]^T (fp32-ish accuracy)
// CTA tile 128x128, BK=64, 8 warps of 32x64, double-buffered cp.async
// SMEM tile layout: [128 rows][64 bf16 + 8 pad] = 144B rows
// ============================================================================
#define TPITCH 144
#define TILE_B (128 * TPITCH)            /* 18432 */
#define STAGE_B (4 * TILE_B)             /* 73728: Ah, Al, Bh, Bl */
#define GSM_TOTAL (2 * STAGE_B)          /* 147456 */

__global__ __launch_bounds__(256) void gemm_bf16s(
        const __nv_bfloat16* __restrict__ Ah, const __nv_bfloat16* __restrict__ Al,
        const __nv_bfloat16* __restrict__ Bh, const __nv_bfloat16* __restrict__ Bl,
        float* __restrict__ C, int M, int N, int K) {
    extern __shared__ char smem[];
    const uint32_t sb = smem_u32(smem);

    const int tid = threadIdx.x;
    const int wid = tid >> 5, lid = tid & 31;
    const int warp_m = wid & 3, warp_n = wid >> 2;
    const int m0 = blockIdx.y * 128, n0 = blockIdx.x * 128;
    const int NKB = K >> 6;

    // loader indexing: 16 chunks of 16B per thread per stage
    // chunkid = tid + j*256 ; tile = chunkid>>10 ; row = (chunkid&1023)>>3 ; c = chunkid&7
    const __nv_bfloat16* srcs[4] = {Ah, Al, Bh, Bl};

    // ldmatrix lane addressing (byte offsets within a tile)
    const int a_row  = (lid & 15);                      // + warp_m*32 + mt*16
    const int a_koff = (lid >> 4) * 8;
    const int b_n    = (lid & 7) + ((lid >> 4) << 3);   // + warp_n*64 + ng*16
    const int b_koff = ((lid >> 3) & 1) * 8;

    float acc[2][8][4];
#pragma unroll
    for (int i = 0; i < 2; i++)
#pragma unroll
        for (int j = 0; j < 8; j++)
#pragma unroll
            for (int k = 0; k < 4; k++) acc[i][j][k] = 0.f;

    // ---- prologue: stage 0 ----
    {
        const int kb = 0;
#pragma unroll
        for (int j = 0; j < 16; j++) {
            int chunkid = tid + j * 256;
            int tile = j >> 2;
            int within = chunkid & 1023;
            int row = within >> 3, c = within & 7;
            int grow = (tile < 2 ? m0 : n0) + row;
            const __nv_bfloat16* src = srcs[tile] + (size_t)grow * K + kb * 64 + c * 8;
            uint32_t dst = sb + tile * TILE_B + row * TPITCH + c * 16;
            CP16(dst, src);
        }
        CP_COMMIT();
    }
    CP_WAIT0();
    __syncthreads();

#pragma unroll 1
    for (int kb = 0; kb < NKB; kb++) {
        const int s = kb & 1;
        const uint32_t stage = sb + s * STAGE_B;

        if (kb + 1 < NKB) {
            const uint32_t nstage = sb + (1 - s) * STAGE_B;
#pragma unroll
            for (int j = 0; j < 16; j++) {
                int chunkid = tid + j * 256;
                int tile = j >> 2;
                int within = chunkid & 1023;
                int row = within >> 3, c = within & 7;
                int grow = (tile < 2 ? m0 : n0) + row;
                const __nv_bfloat16* src = srcs[tile] + (size_t)grow * K + (kb + 1) * 64 + c * 8;
                uint32_t dst = nstage + tile * TILE_B + row * TPITCH + c * 16;
                CP16(dst, src);
            }
            CP_COMMIT();
        }

        const uint32_t tAh = stage;
        const uint32_t tAl = stage + TILE_B;
        const uint32_t tBh = stage + 2 * TILE_B;
        const uint32_t tBl = stage + 3 * TILE_B;

#pragma unroll
        for (int ks = 0; ks < 4; ks++) {
            uint32_t a_hi[2][4], a_lo[2][4];
#pragma unroll
            for (int mt = 0; mt < 2; mt++) {
                uint32_t ao = (uint32_t)((warp_m * 32 + mt * 16 + a_row) * TPITCH +
                                         (ks * 16 + a_koff) * 2);
                ldsm4(a_hi[mt], tAh + ao);
                ldsm4(a_lo[mt], tAl + ao);
            }
#pragma unroll
            for (int ng = 0; ng < 4; ng++) {
                uint32_t bo = (uint32_t)((warp_n * 64 + ng * 16 + b_n) * TPITCH +
                                         (ks * 16 + b_koff) * 2);
                uint32_t bh[4], bl[4];
                ldsm4(bh, tBh + bo);
                ldsm4(bl, tBl + bo);
#pragma unroll
                for (int mt = 0; mt < 2; mt++) {
                    mma16816(acc[mt][ng * 2 + 0], a_hi[mt], &bh[0]);
                    mma16816(acc[mt][ng * 2 + 1], a_hi[mt], &bh[2]);
                    mma16816(acc[mt][ng * 2 + 0], a_hi[mt], &bl[0]);
                    mma16816(acc[mt][ng * 2 + 1], a_hi[mt], &bl[2]);
                    mma16816(acc[mt][ng * 2 + 0], a_lo[mt], &bh[0]);
                    mma16816(acc[mt][ng * 2 + 1], a_lo[mt], &bh[2]);
                }
            }
        }

        if (kb + 1 < NKB) CP_WAIT0();
        __syncthreads();
    }

    // ---- epilogue ----
    const int g = lid >> 2, tg = lid & 3;
#pragma unroll
    for (int mt = 0; mt < 2; mt++) {
#pragma unroll
        for (int ng = 0; ng < 4; ng++) {
#pragma unroll
            for (int half = 0; half < 2; half++) {
                float* d = acc[mt][ng * 2 + half];
                int row0 = m0 + warp_m * 32 + mt * 16 + g;
                int col  = n0 + warp_n * 64 + ng * 16 + half * 8 + tg * 2;
                *(float2*)(C + (size_t)row0 * N + col)       = make_float2(d[0], d[1]);
                *(float2*)(C + (size_t)(row0 + 8) * N + col) = make_float2(d[2], d[3]);
            }
        }
    }
}

// ---------------- per-chunk KV sums ----------------
__global__ __launch_bounds__(256) void chunk_sums() {
    extern __shared__ float sm[];
    float* Ks = sm;
    float* Vs = sm + CHUNK * HS;
    int blk = blockIdx.x;
    int h = blk >> 4, c = blk & 15;
    int t0 = c * CHUNK;
    int tid = threadIdx.x;

    for (int i = tid; i < CHUNK * HS; i += 256) {
        int t = i >> 6, d = i & 63;
        const float* base = g_qkv + (size_t)(t0 + t) * (3 * D_MODEL) + h * HS + d;
        Ks[i] = phi(base[D_MODEL]);
        Vs[i] = base[2 * D_MODEL];
    }
    __syncthreads();

    int d0 = (tid >> 4) * 4, f0 = (tid & 15) * 4;
    float acc[4][4];
#pragma unroll
    for (int i = 0; i < 4; i++)
#pragma unroll
        for (int j = 0; j < 4; j++) acc[i][j] = 0.f;

    for (int t = 0; t < CHUNK; t++) {
        float4 k4 = *(const float4*)&Ks[t * HS + d0];
        float4 v4 = *(const float4*)&Vs[t * HS + f0];
        float kf[4] = {k4.x, k4.y, k4.z, k4.w};
        float vf[4] = {v4.x, v4.y, v4.z, v4.w};
#pragma unroll
        for (int i = 0; i < 4; i++)
#pragma unroll
            for (int j = 0; j < 4; j++)
                acc[i][j] = fmaf(kf[i], vf[j], acc[i][j]);
    }
    float* Sout = g_Sc + (size_t)blk * HS * HS;
#pragma unroll
    for (int i = 0; i < 4; i++)
#pragma unroll
        for (int j = 0; j < 4; j++)
            Sout[(d0 + i) * HS + f0 + j] = acc[i][j];

    if (tid < HS) {
        float z = 0.f;
        for (int t = 0; t < CHUNK; t++) z += Ks[t * HS + tid];
        g_zc[blk * HS + tid] = z;
    }
}

// ---------------- exclusive prefix over chunks ----------------
__global__ __launch_bounds__(256) void chunk_prefix() {
    int h = blockIdx.x;
    for (int i = threadIdx.x; i < HS * HS; i += 256) {
        float run = 0.f;
#pragma unroll
        for (int c = 0; c < NC; c++) {
            size_t idx = (size_t)(h * NC + c) * HS * HS + i;
            g_Sp[idx] = run;
            run += g_Sc[idx];
        }
    }
    if (threadIdx.x < HS) {
        float run = 0.f;
#pragma unroll
        for (int c = 0; c < NC; c++) {
            int idx = (h * NC + c) * HS + threadIdx.x;
            g_zp[idx] = run;
            run += g_zc[idx];
        }
    }
}

// ---------------- per-chunk output ----------------
#define QP 136
#define VP 68
#define AP 132
__global__ __launch_bounds__(256) void attn_out() {
    extern __shared__ float sm[];
    float* Qt  = sm;
    float* Kt  = Qt + HS * QP;
    float* Vs  = Kt + HS * QP;
    float* Am  = Vs + CHUNK * VP;
    float* Sps = Am + CHUNK * AP;
    float* zps = Sps + HS * VP;
    float* den = zps + HS;

    int blk = blockIdx.x;
    int h = blk >> 4, c = blk & 15;
    int t0g = c * CHUNK;
    int tid = threadIdx.x;

    for (int i = tid; i < CHUNK * HS; i += 256) {
        int t = i >> 6, d = i & 63;
        const float* base = g_qkv + (size_t)(t0g + t) * (3 * D_MODEL) + h * HS + d;
        Qt[d * QP + t] = phi(base[0]);
        Kt[d * QP + t] = phi(base[D_MODEL]);
        Vs[t * VP + d] = base[2 * D_MODEL];
    }
    const float* SpG = g_Sp + (size_t)blk * HS * HS;
    for (int i = tid; i < HS * HS; i += 256)
        Sps[(i >> 6) * VP + (i & 63)] = SpG[i];
    if (tid < HS) zps[tid] = g_zp[blk * HS + tid];
    __syncthreads();

    {
        int ty = tid >> 4, tx = tid & 15;
        int tt0 = ty * 8, ss0 = tx * 8;
        float acc[8][8];
#pragma unroll
        for (int i = 0; i < 8; i++)
#pragma unroll
            for (int j = 0; j < 8; j++) acc[i][j] = 0.f;

        for (int d = 0; d < HS; d++) {
            float qf[8], kf[8];
            *(float4*)(qf)     = *(const float4*)&Qt[d * QP + tt0];
            *(float4*)(qf + 4) = *(const float4*)&Qt[d * QP + tt0 + 4];
            *(float4*)(kf)     = *(const float4*)&Kt[d * QP + ss0];
            *(float4*)(kf + 4) = *(const float4*)&Kt[d * QP + ss0 + 4];
#pragma unroll
            for (int i = 0; i < 8; i++)
#pragma unroll
                for (int j = 0; j < 8; j++)
                    acc[i][j] = fmaf(qf[i], kf[j], acc[i][j]);
        }
#pragma unroll
        for (int i = 0; i < 8; i++) {
            int t = tt0 + i;
            float w[8];
#pragma unroll
            for (int j = 0; j < 8; j++)
                w[j] = (ss0 + j <= t) ? acc[i][j] : 0.f;
            *(float4*)&Am[t * AP + ss0]     = make_float4(w[0], w[1], w[2], w[3]);
            *(float4*)&Am[t * AP + ss0 + 4] = make_float4(w[4], w[5], w[6], w[7]);
        }
    }
    __syncthreads();

    if (tid < CHUNK) {
        int t = tid;
        float s = 0.f;
        for (int ss = 0; ss < CHUNK; ss++) s += Am[t * AP + ss];
        float qz = 0.f;
        for (int d = 0; d < HS; d++) qz = fmaf(Qt[d * QP + t], zps[d], qz);
        den[t] = s + qz + EPSF;
    }
    __syncthreads();

    {
        int ty = tid >> 4, tx = tid & 15;
        int tt0 = ty * 8, f0 = tx * 4;
        float acc[8][4];
#pragma unroll
        for (int i = 0; i < 8; i++)
#pragma unroll
            for (int j = 0; j < 4; j++) acc[i][j] = 0.f;

        for (int s = 0; s < CHUNK; s++) {
            float4 v4 = *(const float4*)&Vs[s * VP + f0];
            float vf[4] = {v4.x, v4.y, v4.z, v4.w};
#pragma unroll
            for (int i = 0; i < 8; i++) {
                float a = Am[(tt0 + i) * AP + s];
#pragma unroll
                for (int j = 0; j < 4; j++)
                    acc[i][j] = fmaf(a, vf[j], acc[i][j]);
            }
        }
        for (int d = 0; d < HS; d++) {
            float4 sp4 = *(const float4*)&Sps[d * VP + f0];
            float spf[4] = {sp4.x, sp4.y, sp4.z, sp4.w};
            float qf[8];
            *(float4*)(qf)     = *(const float4*)&Qt[d * QP + tt0];
            *(float4*)(qf + 4) = *(const float4*)&Qt[d * QP + tt0 + 4];
#pragma unroll
            for (int i = 0; i < 8; i++)
#pragma unroll
                for (int j = 0; j < 4; j++)
                    acc[i][j] = fmaf(qf[i], spf[j], acc[i][j]);
        }
#pragma unroll
        for (int i = 0; i < 8; i++) {
            int t = tt0 + i;
            float inv = 1.f / den[t];
            float* dst = g_xo + (size_t)(t0g + t) * D_MODEL + h * HS + f0;
            *(float4*)dst = make_float4(acc[i][0] * inv, acc[i][1] * inv,
                                        acc[i][2] * inv, acc[i][3] * inv);
        }
    }
}

// ---------------- launch ----------------
extern "C" void kernel_launch(void* const* d_in, const int* in_sizes, int n_in,
                              void* d_out, int out_size) {
    const float* x     = (const float*)d_in[0];
    const float* w_qkv = (const float*)d_in[1];
    const float* w_out = (const float*)d_in[2];
    float* out = (float*)d_out;

    float *qkv, *xo;
    cudaGetSymbolAddress((void**)&qkv, g_qkv);
    cudaGetSymbolAddress((void**)&xo,  g_xo);
    __nv_bfloat16 *ah, *al, *b1h, *b1l, *b2h, *b2l;
    cudaGetSymbolAddress((void**)&ah,  g_ah);
    cudaGetSymbolAddress((void**)&al,  g_al);
    cudaGetSymbolAddress((void**)&b1h, g_b1h);
    cudaGetSymbolAddress((void**)&b1l, g_b1l);
    cudaGetSymbolAddress((void**)&b2h, g_b2h);
    cudaGetSymbolAddress((void**)&b2l, g_b2l);

    const int CHUNK_SMEM = 2 * CHUNK * HS * sizeof(float);
    const int ATTN_SMEM  = (HS * QP * 2 + CHUNK * VP + CHUNK * AP +
                            HS * VP + HS + CHUNK) * sizeof(float);
    cudaFuncSetAttribute(gemm_bf16s, cudaFuncAttributeMaxDynamicSharedMemorySize, GSM_TOTAL);
    cudaFuncSetAttribute(chunk_sums, cudaFuncAttributeMaxDynamicSharedMemorySize, CHUNK_SMEM);
    cudaFuncSetAttribute(attn_out,   cudaFuncAttributeMaxDynamicSharedMemorySize, ATTN_SMEM);

    // split inputs
    splitk<<<(T_LEN * D_MODEL / 4 + 255) / 256, 256>>>(x, ah, al, T_LEN * D_MODEL / 4);
    splitk<<<(3 * D_MODEL * D_MODEL / 4 + 255) / 256, 256>>>(w_qkv, b1h, b1l, 3 * D_MODEL * D_MODEL / 4);
    splitk<<<(D_MODEL * D_MODEL / 4 + 255) / 256, 256>>>(w_out, b2h, b2l, D_MODEL * D_MODEL / 4);

    // qkv = x @ w_qkv^T
    dim3 g1(3 * D_MODEL / 128, T_LEN / 128);   // (24, 16)
    gemm_bf16s<<<g1, 256, GSM_TOTAL>>>(ah, al, b1h, b1l, qkv, T_LEN, 3 * D_MODEL, D_MODEL);

    chunk_sums<<<H_NUM * NC, 256, CHUNK_SMEM>>>();
    chunk_prefix<<<H_NUM, 256>>>();
    attn_out<<<H_NUM * NC, 256, ATTN_SMEM>>>();

    // split xo, then out = xo @ w_out^T
    splitk<<<(T_LEN * D_MODEL / 4 + 255) / 256, 256>>>(xo, ah, al, T_LEN * D_MODEL / 4);
    dim3 g2(D_MODEL / 128, T_LEN / 128);       // (8, 16)
    gemm_bf16s<<<g2, 256, GSM_TOTAL>>>(ah, al, b2h, b2l, out, T_LEN, D_MODEL, D_MODEL);
}

// round 4
// speedup vs baseline: 2.0885x; 1.0687x over previous
#include <cuda_runtime.h>
#include <cuda_bf16.h>
#include <cstdint>

#define T_LEN 2048
#define D_MODEL 1024
#define H_NUM 16
#define HS 64
#define CHUNK 128
#define NC (T_LEN / CHUNK)   /* 16 */
#define EPSF 1e-6f

// ---------------- scratch ----------------
__device__ float g_qkv[T_LEN * 3 * D_MODEL];          // [T, 3, H, Hs]
__device__ float g_Sc [H_NUM * NC * HS * HS];
__device__ float g_Sp [H_NUM * NC * HS * HS];
__device__ float g_zc [H_NUM * NC * HS];
__device__ float g_zp [H_NUM * NC * HS];

__device__ __align__(16) __nv_bfloat16 g_ah [T_LEN * D_MODEL];       // A hi (x, then xo)
__device__ __align__(16) __nv_bfloat16 g_al [T_LEN * D_MODEL];       // A lo
__device__ __align__(16) __nv_bfloat16 g_b1h[3 * D_MODEL * D_MODEL];
__device__ __align__(16) __nv_bfloat16 g_b1l[3 * D_MODEL * D_MODEL];
__device__ __align__(16) __nv_bfloat16 g_b2h[D_MODEL * D_MODEL];
__device__ __align__(16) __nv_bfloat16 g_b2l[D_MODEL * D_MODEL];

__device__ __forceinline__ float phi(float x) {
    return x > 0.f ? x + 1.f : expf(x);
}

// ============================================================================
// fp32 -> bf16 (hi, lo)
// ============================================================================
__device__ __forceinline__ void split1(float x, __nv_bfloat16& h, __nv_bfloat16& l) {
    h = __float2bfloat16_rn(x);
    l = __float2bfloat16_rn(x - __bfloat162float(h));
}
// pack two floats -> (hi bf16x2, lo bf16x2)
__device__ __forceinline__ void split2(float a, float b, uint32_t& hi, uint32_t& lo) {
    __nv_bfloat16 ha, la, hb, lb;
    split1(a, ha, la);
    split1(b, hb, lb);
    hi = (uint32_t)__bfloat16_as_ushort(ha) | ((uint32_t)__bfloat16_as_ushort(hb) << 16);
    lo = (uint32_t)__bfloat16_as_ushort(la) | ((uint32_t)__bfloat16_as_ushort(lb) << 16);
}

__global__ __launch_bounds__(256) void splitk(const float* __restrict__ s,
                                              __nv_bfloat16* __restrict__ h,
                                              __nv_bfloat16* __restrict__ l,
                                              int n4) {
    int i = blockIdx.x * 256 + threadIdx.x;
    if (i >= n4) return;
    float4 v = ((const float4*)s)[i];
    uint32_t h01, l01, h23, l23;
    split2(v.x, v.y, h01, l01);
    split2(v.z, v.w, h23, l23);
    ((uint2*)h)[i] = make_uint2(h01, h23);
    ((uint2*)l)[i] = make_uint2(l01, l23);
}

// ============================================================================
// mma.sync helpers
// ============================================================================
__device__ __forceinline__ uint32_t smem_u32(const void* p) {
    uint32_t a;
    asm("{ .reg .u64 t; cvta.to.shared.u64 t, %1; cvt.u32.u64 %0, t; }" : "=r"(a) : "l"(p));
    return a;
}
__device__ __forceinline__ void ldsm4(uint32_t* r, uint32_t addr) {
    asm volatile("ldmatrix.sync.aligned.m8n8.x4.shared.b16 {%0,%1,%2,%3}, [%4];"
                 : "=r"(r[0]), "=r"(r[1]), "=r"(r[2]), "=r"(r[3]) : "r"(addr));
}
__device__ __forceinline__ void mma16816(float* d, const uint32_t* a, const uint32_t* b) {
    asm volatile("mma.sync.aligned.m16n8k16.row.col.f32.bf16.bf16.f32 "
                 "{%0,%1,%2,%3},{%4,%5,%6,%7},{%8,%9},{%0,%1,%2,%3};"
                 : "+f"(d[0]), "+f"(d[1]), "+f"(d[2]), "+f"(d[3])
                 : "r"(a[0]), "r"(a[1]), "r"(a[2]), "r"(a[3]), "r"(b[0]), "r"(b[1]));
}
#define CP16(dst, src) \
    asm volatile("cp.async.cg.shared.global [%0], [%1], 16;" :: "r"(dst), "l"(src) : "memory")
#define CP_COMMIT() asm volatile("cp.async.commit_group;" ::: "memory")
#define CP_WAIT0()  asm volatile("cp.async.wait_group 0;" ::: "memory")

// ============================================================================
// split-bf16 GEMM: C[M][N] = A[M][K] @ B[N][K]^T
// CTA tile 128x128, BK=32, 8 warps of 32x64, double buffer, 2 CTAs/SM
// SMEM tile: [128 rows][32 bf16 (64B) + 16B pad] = 80B pitch
// ============================================================================
#define TPITCH 80
#define TILE_B (128 * TPITCH)            /* 10240 */
#define STAGE_B (4 * TILE_B)             /* 40960: Ah, Al, Bh, Bl */
#define GSM_TOTAL (2 * STAGE_B)          /* 81920 */

__global__ __launch_bounds__(256, 2) void gemm_bf16s(
        const __nv_bfloat16* __restrict__ Ah, const __nv_bfloat16* __restrict__ Al,
        const __nv_bfloat16* __restrict__ Bh, const __nv_bfloat16* __restrict__ Bl,
        float* __restrict__ C, int M, int N, int K) {
    extern __shared__ char smem[];
    const uint32_t sb = smem_u32(smem);

    const int tid = threadIdx.x;
    const int wid = tid >> 5, lid = tid & 31;
    const int warp_m = wid & 3, warp_n = wid >> 2;
    const int m0 = blockIdx.y * 128, n0 = blockIdx.x * 128;
    const int NKB = K >> 5;

    const __nv_bfloat16* srcs[4] = {Ah, Al, Bh, Bl};

    const int a_row  = (lid & 15);
    const int a_koff = (lid >> 4) * 8;
    const int b_n    = (lid & 7) + ((lid >> 4) << 3);
    const int b_koff = ((lid >> 3) & 1) * 8;

    float acc[2][8][4];
#pragma unroll
    for (int i = 0; i < 2; i++)
#pragma unroll
        for (int j = 0; j < 8; j++)
#pragma unroll
            for (int k = 0; k < 4; k++) acc[i][j][k] = 0.f;

    // prologue: stage 0
#pragma unroll
    for (int j = 0; j < 8; j++) {
        int chunkid = tid + j * 256;       // 0..2047
        int tile = chunkid >> 9;           // 512 chunks per tile
        int within = chunkid & 511;
        int row = within >> 2, c = within & 3;
        int grow = (tile < 2 ? m0 : n0) + row;
        const __nv_bfloat16* src = srcs[tile] + (size_t)grow * K + c * 8;
        CP16(sb + tile * TILE_B + row * TPITCH + c * 16, src);
    }
    CP_COMMIT();
    CP_WAIT0();
    __syncthreads();

#pragma unroll 1
    for (int kb = 0; kb < NKB; kb++) {
        const int s = kb & 1;
        const uint32_t stage = sb + s * STAGE_B;

        if (kb + 1 < NKB) {
            const uint32_t nstage = sb + (1 - s) * STAGE_B;
#pragma unroll
            for (int j = 0; j < 8; j++) {
                int chunkid = tid + j * 256;
                int tile = chunkid >> 9;
                int within = chunkid & 511;
                int row = within >> 2, c = within & 3;
                int grow = (tile < 2 ? m0 : n0) + row;
                const __nv_bfloat16* src = srcs[tile] + (size_t)grow * K + (kb + 1) * 32 + c * 8;
                CP16(nstage + tile * TILE_B + row * TPITCH + c * 16, src);
            }
            CP_COMMIT();
        }

        const uint32_t tAh = stage;
        const uint32_t tAl = stage + TILE_B;
        const uint32_t tBh = stage + 2 * TILE_B;
        const uint32_t tBl = stage + 3 * TILE_B;

#pragma unroll
        for (int ks = 0; ks < 2; ks++) {
            uint32_t a_hi[2][4], a_lo[2][4];
#pragma unroll
            for (int mt = 0; mt < 2; mt++) {
                uint32_t ao = (uint32_t)((warp_m * 32 + mt * 16 + a_row) * TPITCH +
                                         (ks * 16 + a_koff) * 2);
                ldsm4(a_hi[mt], tAh + ao);
                ldsm4(a_lo[mt], tAl + ao);
            }
#pragma unroll
            for (int ng = 0; ng < 4; ng++) {
                uint32_t bo = (uint32_t)((warp_n * 64 + ng * 16 + b_n) * TPITCH +
                                         (ks * 16 + b_koff) * 2);
                uint32_t bh[4], bl[4];
                ldsm4(bh, tBh + bo);
                ldsm4(bl, tBl + bo);
#pragma unroll
                for (int mt = 0; mt < 2; mt++) {
                    mma16816(acc[mt][ng * 2 + 0], a_hi[mt], &bh[0]);
                    mma16816(acc[mt][ng * 2 + 1], a_hi[mt], &bh[2]);
                    mma16816(acc[mt][ng * 2 + 0], a_hi[mt], &bl[0]);
                    mma16816(acc[mt][ng * 2 + 1], a_hi[mt], &bl[2]);
                    mma16816(acc[mt][ng * 2 + 0], a_lo[mt], &bh[0]);
                    mma16816(acc[mt][ng * 2 + 1], a_lo[mt], &bh[2]);
                }
            }
        }

        if (kb + 1 < NKB) CP_WAIT0();
        __syncthreads();
    }

    const int g = lid >> 2, tg = lid & 3;
#pragma unroll
    for (int mt = 0; mt < 2; mt++) {
#pragma unroll
        for (int ng = 0; ng < 4; ng++) {
#pragma unroll
            for (int half = 0; half < 2; half++) {
                float* d = acc[mt][ng * 2 + half];
                int row0 = m0 + warp_m * 32 + mt * 16 + g;
                int col  = n0 + warp_n * 64 + ng * 16 + half * 8 + tg * 2;
                *(float2*)(C + (size_t)row0 * N + col)       = make_float2(d[0], d[1]);
                *(float2*)(C + (size_t)(row0 + 8) * N + col) = make_float2(d[2], d[3]);
            }
        }
    }
}

// ---------------- per-chunk KV sums ----------------
__global__ __launch_bounds__(256) void chunk_sums() {
    extern __shared__ float sm[];
    float* Ks = sm;
    float* Vs = sm + CHUNK * HS;
    int blk = blockIdx.x;
    int h = blk >> 4, c = blk & 15;
    int t0 = c * CHUNK;
    int tid = threadIdx.x;

    for (int i = tid; i < CHUNK * HS; i += 256) {
        int t = i >> 6, d = i & 63;
        const float* base = g_qkv + (size_t)(t0 + t) * (3 * D_MODEL) + h * HS + d;
        Ks[i] = phi(base[D_MODEL]);
        Vs[i] = base[2 * D_MODEL];
    }
    __syncthreads();

    int d0 = (tid >> 4) * 4, f0 = (tid & 15) * 4;
    float acc[4][4];
#pragma unroll
    for (int i = 0; i < 4; i++)
#pragma unroll
        for (int j = 0; j < 4; j++) acc[i][j] = 0.f;

    for (int t = 0; t < CHUNK; t++) {
        float4 k4 = *(const float4*)&Ks[t * HS + d0];
        float4 v4 = *(const float4*)&Vs[t * HS + f0];
        float kf[4] = {k4.x, k4.y, k4.z, k4.w};
        float vf[4] = {v4.x, v4.y, v4.z, v4.w};
#pragma unroll
        for (int i = 0; i < 4; i++)
#pragma unroll
            for (int j = 0; j < 4; j++)
                acc[i][j] = fmaf(kf[i], vf[j], acc[i][j]);
    }
    float* Sout = g_Sc + (size_t)blk * HS * HS;
#pragma unroll
    for (int i = 0; i < 4; i++)
#pragma unroll
        for (int j = 0; j < 4; j++)
            Sout[(d0 + i) * HS + f0 + j] = acc[i][j];

    if (tid < HS) {
        float z = 0.f;
        for (int t = 0; t < CHUNK; t++) z += Ks[t * HS + tid];
        g_zc[blk * HS + tid] = z;
    }
}

// ---------------- exclusive prefix over chunks ----------------
__global__ __launch_bounds__(256) void chunk_prefix() {
    int h = blockIdx.x;
    for (int i = threadIdx.x; i < HS * HS; i += 256) {
        float run = 0.f;
#pragma unroll
        for (int c = 0; c < NC; c++) {
            size_t idx = (size_t)(h * NC + c) * HS * HS + i;
            g_Sp[idx] = run;
            run += g_Sc[idx];
        }
    }
    if (threadIdx.x < HS) {
        float run = 0.f;
#pragma unroll
        for (int c = 0; c < NC; c++) {
            int idx = (h * NC + c) * HS + threadIdx.x;
            g_zp[idx] = run;
            run += g_zc[idx];
        }
    }
}

// ============================================================================
// attention per chunk, mma-based.
// Per block (h,c): A = phi(Q) phi(K)^T (causal), rowsum; O = A V + Q [Sp|zp];
// out = O / (rowsum + qz + eps), written pre-split (bf16 hi/lo) to g_ah/g_al.
// SMEM (bf16): Qh/Ql [128][72], Kh/Kl [128][72], Vth/Vtl [64][136] (transposed),
//              Spth/Sptl [80][72] (transposed Sp; row 64 = zp; rows 65-79 zero)
// ============================================================================
#define QKP 72
#define VTP 136
#define SPP 72
#define OFF_QH 0
#define OFF_QL (128 * QKP)
#define OFF_KH (2 * 128 * QKP)
#define OFF_KL (3 * 128 * QKP)
#define OFF_VTH (4 * 128 * QKP)
#define OFF_VTL (OFF_VTH + 64 * VTP)
#define OFF_SPH (OFF_VTL + 64 * VTP)
#define OFF_SPL (OFF_SPH + 80 * SPP)
#define ATTN_SMEM_ELEMS (OFF_SPL + 80 * SPP)
#define ATTN_SMEM_B (ATTN_SMEM_ELEMS * 2)

__global__ __launch_bounds__(256) void attn_mma() {
    extern __shared__ __nv_bfloat16 sma[];
    const uint32_t sb = smem_u32(sma);

    const int blk = blockIdx.x;
    const int h = blk >> 4, c = blk & 15;
    const int t0g = c * CHUNK;
    const int tid = threadIdx.x;
    const int w = tid >> 5, lid = tid & 31;

    // ---- load / transform ----
    for (int i = tid; i < CHUNK * HS; i += 256) {
        int t = i >> 6, d = i & 63;
        const float* base = g_qkv + (size_t)(t0g + t) * (3 * D_MODEL) + h * HS + d;
        __nv_bfloat16 hh, ll;
        split1(phi(base[0]), hh, ll);
        sma[OFF_QH + t * QKP + d] = hh;
        sma[OFF_QL + t * QKP + d] = ll;
        split1(phi(base[D_MODEL]), hh, ll);
        sma[OFF_KH + t * QKP + d] = hh;
        sma[OFF_KL + t * QKP + d] = ll;
        split1(base[2 * D_MODEL], hh, ll);
        sma[OFF_VTH + d * VTP + t] = hh;
        sma[OFF_VTL + d * VTP + t] = ll;
    }
    const float* SpG = g_Sp + (size_t)blk * HS * HS;
    const float* zpG = g_zp + (size_t)blk * HS;
    for (int i = tid; i < HS * HS; i += 256) {
        int d = i >> 6, f = i & 63;
        __nv_bfloat16 hh, ll;
        split1(SpG[i], hh, ll);
        sma[OFF_SPH + f * SPP + d] = hh;
        sma[OFF_SPL + f * SPP + d] = ll;
    }
    for (int i = tid; i < 16 * SPP; i += 256) {
        int r = 64 + i / SPP, d = i % SPP;
        float v = (r == 64 && d < 64) ? zpG[d] : 0.f;
        __nv_bfloat16 hh, ll;
        split1(v, hh, ll);
        sma[OFF_SPH + r * SPP + d] = hh;
        sma[OFF_SPL + r * SPP + d] = ll;
    }
    __syncthreads();

    // ldmatrix lane addressing
    const int a_row  = lid & 15;
    const int a_ko   = (lid >> 4) * 16;              // bytes
    const int b_n    = (lid & 7) + ((lid >> 4) << 3);
    const int b_ko   = ((lid >> 3) & 1) * 16;        // bytes
    const int g = lid >> 2, tq = lid & 3;

    // ---- step 1: A = Q K^T (split, 3 products), acc fp32 ----
    float ca[16][4];
#pragma unroll
    for (int j = 0; j < 16; j++)
#pragma unroll
        for (int e = 0; e < 4; e++) ca[j][e] = 0.f;

#pragma unroll
    for (int ks = 0; ks < 4; ks++) {
        uint32_t aqh[4], aql[4];
        uint32_t ao = (uint32_t)((w * 16 + a_row) * (QKP * 2) + ks * 32 + a_ko);
        ldsm4(aqh, sb + OFF_QH * 2 + ao);
        ldsm4(aql, sb + OFF_QL * 2 + ao);
#pragma unroll
        for (int sg = 0; sg < 8; sg++) {
            uint32_t bo = (uint32_t)((sg * 16 + b_n) * (QKP * 2) + ks * 32 + b_ko);
            uint32_t bkh[4], bkl[4];
            ldsm4(bkh, sb + OFF_KH * 2 + bo);
            ldsm4(bkl, sb + OFF_KL * 2 + bo);
            mma16816(ca[sg * 2 + 0], aqh, &bkh[0]);
            mma16816(ca[sg * 2 + 1], aqh, &bkh[2]);
            mma16816(ca[sg * 2 + 0], aqh, &bkl[0]);
            mma16816(ca[sg * 2 + 1], aqh, &bkl[2]);
            mma16816(ca[sg * 2 + 0], aql, &bkh[0]);
            mma16816(ca[sg * 2 + 1], aql, &bkh[2]);
        }
    }

    // ---- step 2: causal mask + rowsum ----
    const int row_lo = w * 16 + g, row_hi = row_lo + 8;
    float s_lo = 0.f, s_hi = 0.f;
#pragma unroll
    for (int j = 0; j < 16; j++) {
        int c0 = j * 8 + tq * 2;
        if (c0     > row_lo) ca[j][0] = 0.f;
        if (c0 + 1 > row_lo) ca[j][1] = 0.f;
        if (c0     > row_hi) ca[j][2] = 0.f;
        if (c0 + 1 > row_hi) ca[j][3] = 0.f;
        s_lo += ca[j][0] + ca[j][1];
        s_hi += ca[j][2] + ca[j][3];
    }
    s_lo += __shfl_xor_sync(0xffffffffu, s_lo, 1);
    s_lo += __shfl_xor_sync(0xffffffffu, s_lo, 2);
    s_hi += __shfl_xor_sync(0xffffffffu, s_hi, 1);
    s_hi += __shfl_xor_sync(0xffffffffu, s_hi, 2);

    // ---- step 3: O = A V (+ later Q [Sp|zp]) ----
    float co[9][4];
#pragma unroll
    for (int j = 0; j < 9; j++)
#pragma unroll
        for (int e = 0; e < 4; e++) co[j][e] = 0.f;

#pragma unroll
    for (int ks2 = 0; ks2 < 8; ks2++) {
        // convert A tiles [ks2*2, ks2*2+1] -> A-operand frags (hi/lo)
        uint32_t ahf[4], alf[4];
        split2(ca[ks2 * 2 + 0][0], ca[ks2 * 2 + 0][1], ahf[0], alf[0]);
        split2(ca[ks2 * 2 + 0][2], ca[ks2 * 2 + 0][3], ahf[1], alf[1]);
        split2(ca[ks2 * 2 + 1][0], ca[ks2 * 2 + 1][1], ahf[2], alf[2]);
        split2(ca[ks2 * 2 + 1][2], ca[ks2 * 2 + 1][3], ahf[3], alf[3]);
#pragma unroll
        for (int fg = 0; fg < 4; fg++) {
            uint32_t bo = (uint32_t)((fg * 16 + b_n) * (VTP * 2) + ks2 * 32 + b_ko);
            uint32_t bvh[4], bvl[4];
            ldsm4(bvh, sb + OFF_VTH * 2 + bo);
            ldsm4(bvl, sb + OFF_VTL * 2 + bo);
            mma16816(co[fg * 2 + 0], ahf, &bvh[0]);
            mma16816(co[fg * 2 + 1], ahf, &bvh[2]);
            mma16816(co[fg * 2 + 0], ahf, &bvl[0]);
            mma16816(co[fg * 2 + 1], ahf, &bvl[2]);
            mma16816(co[fg * 2 + 0], alf, &bvh[0]);
            mma16816(co[fg * 2 + 1], alf, &bvh[2]);
        }
    }

    // ---- step 4: O += Q [Sp | zp] ----
#pragma unroll
    for (int ks = 0; ks < 4; ks++) {
        uint32_t aqh[4], aql[4];
        uint32_t ao = (uint32_t)((w * 16 + a_row) * (QKP * 2) + ks * 32 + a_ko);
        ldsm4(aqh, sb + OFF_QH * 2 + ao);
        ldsm4(aql, sb + OFF_QL * 2 + ao);
#pragma unroll
        for (int fg = 0; fg < 5; fg++) {
            uint32_t bo = (uint32_t)((fg * 16 + b_n) * (SPP * 2) + ks * 32 + b_ko);
            uint32_t bsh[4], bsl[4];
            ldsm4(bsh, sb + OFF_SPH * 2 + bo);
            ldsm4(bsl, sb + OFF_SPL * 2 + bo);
            mma16816(co[fg * 2 + 0], aqh, &bsh[0]);
            mma16816(co[fg * 2 + 0], aqh, &bsl[0]);
            mma16816(co[fg * 2 + 0], aql, &bsh[0]);
            if (fg < 4) {
                mma16816(co[fg * 2 + 1], aqh, &bsh[2]);
                mma16816(co[fg * 2 + 1], aqh, &bsl[2]);
                mma16816(co[fg * 2 + 1], aql, &bsh[2]);
            }
        }
    }

    // ---- step 5: denominator, divide, write pre-split xo ----
    float qz_lo = __shfl_sync(0xffffffffu, co[8][0], lid & ~3);
    float qz_hi = __shfl_sync(0xffffffffu, co[8][2], lid & ~3);
    float inv_lo = 1.f / (s_lo + qz_lo + EPSF);
    float inv_hi = 1.f / (s_hi + qz_hi + EPSF);

#pragma unroll
    for (int j = 0; j < 8; j++) {
        int col = h * HS + j * 8 + tq * 2;
        size_t i_lo = (size_t)(t0g + row_lo) * D_MODEL + col;
        size_t i_hi = (size_t)(t0g + row_hi) * D_MODEL + col;
        uint32_t hw, lw;
        split2(co[j][0] * inv_lo, co[j][1] * inv_lo, hw, lw);
        *(uint32_t*)(g_ah + i_lo) = hw;
        *(uint32_t*)(g_al + i_lo) = lw;
        split2(co[j][2] * inv_hi, co[j][3] * inv_hi, hw, lw);
        *(uint32_t*)(g_ah + i_hi) = hw;
        *(uint32_t*)(g_al + i_hi) = lw;
    }
}

// ---------------- launch ----------------
extern "C" void kernel_launch(void* const* d_in, const int* in_sizes, int n_in,
                              void* d_out, int out_size) {
    const float* x     = (const float*)d_in[0];
    const float* w_qkv = (const float*)d_in[1];
    const float* w_out = (const float*)d_in[2];
    float* out = (float*)d_out;

    float* qkv;
    cudaGetSymbolAddress((void**)&qkv, g_qkv);
    __nv_bfloat16 *ah, *al, *b1h, *b1l, *b2h, *b2l;
    cudaGetSymbolAddress((void**)&ah,  g_ah);
    cudaGetSymbolAddress((void**)&al,  g_al);
    cudaGetSymbolAddress((void**)&b1h, g_b1h);
    cudaGetSymbolAddress((void**)&b1l, g_b1l);
    cudaGetSymbolAddress((void**)&b2h, g_b2h);
    cudaGetSymbolAddress((void**)&b2l, g_b2l);

    const int CHUNK_SMEM = 2 * CHUNK * HS * sizeof(float);
    cudaFuncSetAttribute(gemm_bf16s, cudaFuncAttributeMaxDynamicSharedMemorySize, GSM_TOTAL);
    cudaFuncSetAttribute(chunk_sums, cudaFuncAttributeMaxDynamicSharedMemorySize, CHUNK_SMEM);
    cudaFuncSetAttribute(attn_mma,   cudaFuncAttributeMaxDynamicSharedMemorySize, ATTN_SMEM_B);

    splitk<<<(T_LEN * D_MODEL / 4 + 255) / 256, 256>>>(x, ah, al, T_LEN * D_MODEL / 4);
    splitk<<<(3 * D_MODEL * D_MODEL / 4 + 255) / 256, 256>>>(w_qkv, b1h, b1l, 3 * D_MODEL * D_MODEL / 4);
    splitk<<<(D_MODEL * D_MODEL / 4 + 255) / 256, 256>>>(w_out, b2h, b2l, D_MODEL * D_MODEL / 4);

    dim3 g1(3 * D_MODEL / 128, T_LEN / 128);   // (24, 16)
    gemm_bf16s<<<g1, 256, GSM_TOTAL>>>(ah, al, b1h, b1l, qkv, T_LEN, 3 * D_MODEL, D_MODEL);

    chunk_sums<<<H_NUM * NC, 256, CHUNK_SMEM>>>();
    chunk_prefix<<<H_NUM, 256>>>();
    attn_mma<<<H_NUM * NC, 256, ATTN_SMEM_B>>>();   // writes xo pre-split into ah/al

    dim3 g2(D_MODEL / 128, T_LEN / 128);       // (8, 16)
    gemm_bf16s<<<g2, 256, GSM_TOTAL>>>(ah, al, b2h, b2l, out, T_LEN, D_MODEL, D_MODEL);
}

// round 5
// speedup vs baseline: 2.3657x; 1.1327x over previous
#include <cuda_runtime.h>
#include <cuda_bf16.h>
#include <cstdint>

#define T_LEN 2048
#define D_MODEL 1024
#define H_NUM 16
#define HS 64
#define CHUNK 128
#define NC 16
#define EPSF 1e-6f
#define SCP 80   /* Sc/Sp col count: 64 data + zc/zp at col 64 + 15 zero */

// ---------------- scratch (static device globals) ----------------
__device__ float g_Sc [H_NUM * NC * HS * SCP];                        // per-chunk K^T V (+zc col)
__device__ __align__(16) __nv_bfloat16 g_sph[H_NUM * NC * HS * SCP];  // prefix, split hi
__device__ __align__(16) __nv_bfloat16 g_spl[H_NUM * NC * HS * SCP];  // prefix, split lo

__device__ __align__(16) __nv_bfloat16 g_qkvh[3][H_NUM][T_LEN][HS];   // phi(q),phi(k),v hi
__device__ __align__(16) __nv_bfloat16 g_qkvl[3][H_NUM][T_LEN][HS];   // lo

__device__ __align__(16) __nv_bfloat16 g_ah [T_LEN * D_MODEL];        // A hi (x, then xo)
__device__ __align__(16) __nv_bfloat16 g_al [T_LEN * D_MODEL];
__device__ __align__(16) __nv_bfloat16 g_b1h[3 * D_MODEL * D_MODEL];
__device__ __align__(16) __nv_bfloat16 g_b1l[3 * D_MODEL * D_MODEL];
__device__ __align__(16) __nv_bfloat16 g_b2h[D_MODEL * D_MODEL];
__device__ __align__(16) __nv_bfloat16 g_b2l[D_MODEL * D_MODEL];

__device__ __forceinline__ float phi(float x) {
    return x > 0.f ? x + 1.f : expf(x);
}

// ---------------- fp32 -> bf16 (hi, lo) ----------------
__device__ __forceinline__ void split1(float x, __nv_bfloat16& h, __nv_bfloat16& l) {
    h = __float2bfloat16_rn(x);
    l = __float2bfloat16_rn(x - __bfloat162float(h));
}
__device__ __forceinline__ void split2(float a, float b, uint32_t& hi, uint32_t& lo) {
    __nv_bfloat16 ha, la, hb, lb;
    split1(a, ha, la);
    split1(b, hb, lb);
    hi = (uint32_t)__bfloat16_as_ushort(ha) | ((uint32_t)__bfloat16_as_ushort(hb) << 16);
    lo = (uint32_t)__bfloat16_as_ushort(la) | ((uint32_t)__bfloat16_as_ushort(lb) << 16);
}

__global__ __launch_bounds__(256) void splitk(const float* __restrict__ s,
                                              __nv_bfloat16* __restrict__ h,
                                              __nv_bfloat16* __restrict__ l,
                                              int n4) {
    int i = blockIdx.x * 256 + threadIdx.x;
    if (i >= n4) return;
    float4 v = ((const float4*)s)[i];
    uint32_t h01, l01, h23, l23;
    split2(v.x, v.y, h01, l01);
    split2(v.z, v.w, h23, l23);
    ((uint2*)h)[i] = make_uint2(h01, h23);
    ((uint2*)l)[i] = make_uint2(l01, l23);
}

// ---------------- mma helpers ----------------
__device__ __forceinline__ uint32_t smem_u32(const void* p) {
    uint32_t a;
    asm("{ .reg .u64 t; cvta.to.shared.u64 t, %1; cvt.u32.u64 %0, t; }" : "=r"(a) : "l"(p));
    return a;
}
__device__ __forceinline__ void ldsm4(uint32_t* r, uint32_t addr) {
    asm volatile("ldmatrix.sync.aligned.m8n8.x4.shared.b16 {%0,%1,%2,%3}, [%4];"
                 : "=r"(r[0]), "=r"(r[1]), "=r"(r[2]), "=r"(r[3]) : "r"(addr));
}
__device__ __forceinline__ void ldsm4t(uint32_t* r, uint32_t addr) {
    asm volatile("ldmatrix.sync.aligned.m8n8.x4.trans.shared.b16 {%0,%1,%2,%3}, [%4];"
                 : "=r"(r[0]), "=r"(r[1]), "=r"(r[2]), "=r"(r[3]) : "r"(addr));
}
__device__ __forceinline__ void mma16816(float* d, const uint32_t* a, const uint32_t* b) {
    asm volatile("mma.sync.aligned.m16n8k16.row.col.f32.bf16.bf16.f32 "
                 "{%0,%1,%2,%3},{%4,%5,%6,%7},{%8,%9},{%0,%1,%2,%3};"
                 : "+f"(d[0]), "+f"(d[1]), "+f"(d[2]), "+f"(d[3])
                 : "r"(a[0]), "r"(a[1]), "r"(a[2]), "r"(a[3]), "r"(b[0]), "r"(b[1]));
}
#define CP16(dst, src) \
    asm volatile("cp.async.cg.shared.global [%0], [%1], 16;" :: "r"(dst), "l"(src) : "memory")
#define CP_COMMIT() asm volatile("cp.async.commit_group;" ::: "memory")
#define CP_WAIT0()  asm volatile("cp.async.wait_group 0;" ::: "memory")

// ============================================================================
// split-bf16 GEMM: C = A[M][K] @ B[N][K]^T. CTA 128x128, 4 warps of 64x64,
// BK=32, double buffer, 2 CTA/SM. EPI=1: fused phi + split -> g_qkv{h,l}.
// ============================================================================
#define TPITCH 80                        /* 32 bf16 + 16B pad */
#define TILE_B (128 * TPITCH)            /* 10240 */
#define STAGE_B (4 * TILE_B)             /* 40960 */
#define GSM_TOTAL (2 * STAGE_B)          /* 81920 */

template<int EPI>
__global__ __launch_bounds__(128, 2) void gemm_bf16s(
        const __nv_bfloat16* __restrict__ Ah, const __nv_bfloat16* __restrict__ Al,
        const __nv_bfloat16* __restrict__ Bh, const __nv_bfloat16* __restrict__ Bl,
        float* __restrict__ C, int M, int N, int K) {
    extern __shared__ char smem[];
    const uint32_t sb = smem_u32(smem);

    const int tid = threadIdx.x;
    const int wid = tid >> 5, lid = tid & 31;
    const int warp_m = wid & 1, warp_n = wid >> 1;
    const int m0 = blockIdx.y * 128, n0 = blockIdx.x * 128;
    const int NKB = K >> 5;

    const __nv_bfloat16* srcs[4] = {Ah, Al, Bh, Bl};

    const int a_row  = lid & 15;
    const int a_koff = (lid >> 4) * 8;
    const int b_n    = (lid & 7) + ((lid >> 4) << 3);
    const int b_ko   = ((lid >> 3) & 1) * 8;
    const int g = lid >> 2, tg = lid & 3;

    float acc[4][8][4];
#pragma unroll
    for (int i = 0; i < 4; i++)
#pragma unroll
        for (int j = 0; j < 8; j++)
#pragma unroll
            for (int k = 0; k < 4; k++) acc[i][j][k] = 0.f;

    // prologue: stage 0 (2048 chunks of 16B, 16 per thread)
#pragma unroll
    for (int j = 0; j < 16; j++) {
        int chunkid = tid + j * 128;
        int tile = chunkid >> 9;
        int within = chunkid & 511;
        int row = within >> 2, c = within & 3;
        int grow = (tile < 2 ? m0 : n0) + row;
        CP16(sb + tile * TILE_B + row * TPITCH + c * 16,
             srcs[tile] + (size_t)grow * K + c * 8);
    }
    CP_COMMIT();
    CP_WAIT0();
    __syncthreads();

#pragma unroll 1
    for (int kb = 0; kb < NKB; kb++) {
        const int s = kb & 1;
        const uint32_t stage = sb + s * STAGE_B;

        if (kb + 1 < NKB) {
            const uint32_t nstage = sb + (1 - s) * STAGE_B;
#pragma unroll
            for (int j = 0; j < 16; j++) {
                int chunkid = tid + j * 128;
                int tile = chunkid >> 9;
                int within = chunkid & 511;
                int row = within >> 2, c = within & 3;
                int grow = (tile < 2 ? m0 : n0) + row;
                CP16(nstage + tile * TILE_B + row * TPITCH + c * 16,
                     srcs[tile] + (size_t)grow * K + (kb + 1) * 32 + c * 8);
            }
            CP_COMMIT();
        }

        const uint32_t tAh = stage;
        const uint32_t tAl = stage + TILE_B;
        const uint32_t tBh = stage + 2 * TILE_B;
        const uint32_t tBl = stage + 3 * TILE_B;

#pragma unroll
        for (int ks = 0; ks < 2; ks++) {
            uint32_t a_h[4][4], a_l[4][4];
#pragma unroll
            for (int mt = 0; mt < 4; mt++) {
                uint32_t ao = (uint32_t)((warp_m * 64 + mt * 16 + a_row) * TPITCH +
                                         (ks * 16 + a_koff) * 2);
                ldsm4(a_h[mt], tAh + ao);
                ldsm4(a_l[mt], tAl + ao);
            }
#pragma unroll
            for (int ng = 0; ng < 4; ng++) {
                uint32_t bo = (uint32_t)((warp_n * 64 + ng * 16 + b_n) * TPITCH +
                                         (ks * 16 + b_ko) * 2);
                uint32_t bh[4], bl[4];
                ldsm4(bh, tBh + bo);
                ldsm4(bl, tBl + bo);
                // product hh: 8 mmas, all distinct accs
#pragma unroll
                for (int mt = 0; mt < 4; mt++) {
                    mma16816(acc[mt][ng * 2 + 0], a_h[mt], &bh[0]);
                    mma16816(acc[mt][ng * 2 + 1], a_h[mt], &bh[2]);
                }
                // product hl
#pragma unroll
                for (int mt = 0; mt < 4; mt++) {
                    mma16816(acc[mt][ng * 2 + 0], a_h[mt], &bl[0]);
                    mma16816(acc[mt][ng * 2 + 1], a_h[mt], &bl[2]);
                }
                // product lh
#pragma unroll
                for (int mt = 0; mt < 4; mt++) {
                    mma16816(acc[mt][ng * 2 + 0], a_l[mt], &bh[0]);
                    mma16816(acc[mt][ng * 2 + 1], a_l[mt], &bh[2]);
                }
            }
        }

        if (kb + 1 < NKB) CP_WAIT0();
        __syncthreads();
    }

    // ---- epilogue ----
    if (EPI) {
#pragma unroll
        for (int mt = 0; mt < 4; mt++) {
#pragma unroll
            for (int j = 0; j < 8; j++) {
                float* d = acc[mt][j];
                int n = n0 + warp_n * 64 + j * 8 + tg * 2;
                int sq = n >> 10, hh2 = (n >> 6) & 15, dd = n & 63;
                int r0 = m0 + warp_m * 64 + mt * 16 + g;
                float v0 = d[0], v1 = d[1], v2 = d[2], v3 = d[3];
                if (sq < 2) { v0 = phi(v0); v1 = phi(v1); v2 = phi(v2); v3 = phi(v3); }
                uint32_t hw, lw;
                split2(v0, v1, hw, lw);
                *(uint32_t*)&g_qkvh[sq][hh2][r0][dd] = hw;
                *(uint32_t*)&g_qkvl[sq][hh2][r0][dd] = lw;
                split2(v2, v3, hw, lw);
                *(uint32_t*)&g_qkvh[sq][hh2][r0 + 8][dd] = hw;
                *(uint32_t*)&g_qkvl[sq][hh2][r0 + 8][dd] = lw;
            }
        }
    } else {
#pragma unroll
        for (int mt = 0; mt < 4; mt++) {
#pragma unroll
            for (int j = 0; j < 8; j++) {
                float* d = acc[mt][j];
                int r0 = m0 + warp_m * 64 + mt * 16 + g;
                int col = n0 + warp_n * 64 + j * 8 + tg * 2;
                *(float2*)(C + (size_t)r0 * N + col)       = make_float2(d[0], d[1]);
                *(float2*)(C + (size_t)(r0 + 8) * N + col) = make_float2(d[2], d[3]);
            }
        }
    }
}

// ---------------- per-chunk KV sums: Sc[d][f] = sum_t K[t][d] V[t][f]; col 64 = zc ----
__global__ __launch_bounds__(256) void chunk_sums() {
    extern __shared__ float sm[];
    float* Ks = sm;                  // [128][64]
    float* Vs = sm + CHUNK * HS;     // [128][64]
    int blk = blockIdx.x;
    int h = blk >> 4, cc = blk & 15;
    int t0 = cc * CHUNK;
    int tid = threadIdx.x;

    for (int i = tid; i < CHUNK * HS; i += 256) {
        int t = i >> 6, d = i & 63;
        Ks[i] = __bfloat162float(g_qkvh[1][h][t0 + t][d]) +
                __bfloat162float(g_qkvl[1][h][t0 + t][d]);
        Vs[i] = __bfloat162float(g_qkvh[2][h][t0 + t][d]) +
                __bfloat162float(g_qkvl[2][h][t0 + t][d]);
    }
    __syncthreads();

    int d0 = (tid >> 4) * 4, f0 = (tid & 15) * 4;
    float acc[4][4];
#pragma unroll
    for (int i = 0; i < 4; i++)
#pragma unroll
        for (int j = 0; j < 4; j++) acc[i][j] = 0.f;

    for (int t = 0; t < CHUNK; t++) {
        float4 k4 = *(const float4*)&Ks[t * HS + d0];
        float4 v4 = *(const float4*)&Vs[t * HS + f0];
        float kf[4] = {k4.x, k4.y, k4.z, k4.w};
        float vf[4] = {v4.x, v4.y, v4.z, v4.w};
#pragma unroll
        for (int i = 0; i < 4; i++)
#pragma unroll
            for (int j = 0; j < 4; j++)
                acc[i][j] = fmaf(kf[i], vf[j], acc[i][j]);
    }
    float* Sout = g_Sc + (size_t)blk * HS * SCP;
#pragma unroll
    for (int i = 0; i < 4; i++)
#pragma unroll
        for (int j = 0; j < 4; j++)
            Sout[(d0 + i) * SCP + f0 + j] = acc[i][j];

    if (tid < HS) {
        float z = 0.f;
        for (int t = 0; t < CHUNK; t++) z += Ks[t * HS + tid];
        Sout[tid * SCP + 64] = z;
    }
    for (int i = tid; i < HS * 15; i += 256) {
        int r = i / 15, c2 = 65 + i % 15;
        Sout[r * SCP + c2] = 0.f;
    }
}

// ---------------- exclusive prefix over chunks -> split bf16 Sp ----------------
__global__ __launch_bounds__(256) void chunk_prefix() {
    int h = blockIdx.x / 20;
    int e = (blockIdx.x % 20) * 256 + threadIdx.x;   // 0..5119
    float run = 0.f;
#pragma unroll
    for (int c = 0; c < NC; c++) {
        size_t idx = (size_t)(h * NC + c) * (HS * SCP) + e;
        __nv_bfloat16 hh, ll;
        split1(run, hh, ll);
        g_sph[idx] = hh;
        g_spl[idx] = ll;
        run += g_Sc[idx];
    }
}

// ============================================================================
// attention per chunk: A = QK^T (causal) via mma; O = A V + Q [Sp|zp]; divide.
// All operands bf16-split in smem via cp.async; V and Sp read with ldsm.trans.
// smem: qh,ql,kh,kl,vh,vl [128][72]; sph,spl [64][88] (cols 0-79 data)
// ============================================================================
#define QVP 144                          /* bytes per row (72 bf16) */
#define SPB 176                          /* bytes per row (88 bf16) */
#define OFF_QH 0
#define OFF_QL (1 * 128 * QVP)
#define OFF_KH (2 * 128 * QVP)
#define OFF_KL (3 * 128 * QVP)
#define OFF_VH (4 * 128 * QVP)
#define OFF_VL (5 * 128 * QVP)
#define OFF_SPH (6 * 128 * QVP)
#define OFF_SPL (OFF_SPH + 64 * SPB)
#define ATTN_SMEM_B (OFF_SPL + 64 * SPB)  /* 133120 */

__global__ __launch_bounds__(256) void attn_mma() {
    extern __shared__ char smc[];
    const uint32_t sb = smem_u32(smc);

    const int blk = blockIdx.x;
    const int h = blk >> 4, cc = blk & 15;
    const int t0g = cc * CHUNK;
    const int tid = threadIdx.x;
    const int w = tid >> 5, lid = tid & 31;

    // ---- async loads ----
#pragma unroll
    for (int j = 0; j < 24; j++) {                 // 6 bufs x 128 rows x 8 chunks
        int chunkid = tid + j * 256;
        int buf = chunkid >> 10;
        int within = chunkid & 1023;
        int row = within >> 3, c = within & 7;
        int sidx = buf >> 1;
        const __nv_bfloat16* srcp = (buf & 1) ? &g_qkvl[sidx][h][t0g + row][0]
                                              : &g_qkvh[sidx][h][t0g + row][0];
        CP16(sb + buf * (128 * QVP) + row * QVP + c * 16, srcp + c * 8);
    }
#pragma unroll
    for (int j = 0; j < 5; j++) {                  // 2 bufs x 64 rows x 10 chunks
        int chunkid = tid + j * 256;
        int buf = chunkid / 640;
        int within = chunkid % 640;
        int row = within / 10, c = within % 10;
        const __nv_bfloat16* srcp = (buf ? g_spl : g_sph) + (size_t)blk * (HS * SCP) + row * SCP + c * 8;
        CP16(sb + OFF_SPH + buf * (64 * SPB) + row * SPB + c * 16, srcp);
    }
    CP_COMMIT();
    CP_WAIT0();
    __syncthreads();

    const int a_row  = lid & 15;
    const int a_koff = (lid >> 4) * 8;
    const int b_n    = (lid & 7) + ((lid >> 4) << 3);
    const int b_ko   = ((lid >> 3) & 1) * 8;
    const int t_row  = lid & 15;                   // trans-ldsm: k rows
    const int t_col  = ((lid >> 4) << 3);          // trans-ldsm: n col offset
    const int g = lid >> 2, tq = lid & 3;

    // ---- step 1: A = Q K^T ----
    float ca[16][4];
#pragma unroll
    for (int j = 0; j < 16; j++)
#pragma unroll
        for (int e = 0; e < 4; e++) ca[j][e] = 0.f;

#pragma unroll
    for (int ks = 0; ks < 4; ks++) {
        uint32_t aqh[4], aql[4];
        uint32_t ao = (uint32_t)((w * 16 + a_row) * QVP + (ks * 16 + a_koff) * 2);
        ldsm4(aqh, sb + OFF_QH + ao);
        ldsm4(aql, sb + OFF_QL + ao);
#pragma unroll
        for (int sg = 0; sg < 8; sg++) {
            uint32_t bo = (uint32_t)((sg * 16 + b_n) * QVP + (ks * 16 + b_ko) * 2);
            uint32_t bkh[4], bkl[4];
            ldsm4(bkh, sb + OFF_KH + bo);
            ldsm4(bkl, sb + OFF_KL + bo);
            mma16816(ca[sg * 2 + 0], aqh, &bkh[0]);
            mma16816(ca[sg * 2 + 1], aqh, &bkh[2]);
            mma16816(ca[sg * 2 + 0], aqh, &bkl[0]);
            mma16816(ca[sg * 2 + 1], aqh, &bkl[2]);
            mma16816(ca[sg * 2 + 0], aql, &bkh[0]);
            mma16816(ca[sg * 2 + 1], aql, &bkh[2]);
        }
    }

    // ---- step 2: causal mask + rowsum ----
    const int row_lo = w * 16 + g, row_hi = row_lo + 8;
    float s_lo = 0.f, s_hi = 0.f;
#pragma unroll
    for (int j = 0; j < 16; j++) {
        int c0 = j * 8 + tq * 2;
        if (c0     > row_lo) ca[j][0] = 0.f;
        if (c0 + 1 > row_lo) ca[j][1] = 0.f;
        if (c0     > row_hi) ca[j][2] = 0.f;
        if (c0 + 1 > row_hi) ca[j][3] = 0.f;
        s_lo += ca[j][0] + ca[j][1];
        s_hi += ca[j][2] + ca[j][3];
    }
    s_lo += __shfl_xor_sync(0xffffffffu, s_lo, 1);
    s_lo += __shfl_xor_sync(0xffffffffu, s_lo, 2);
    s_hi += __shfl_xor_sync(0xffffffffu, s_hi, 1);
    s_hi += __shfl_xor_sync(0xffffffffu, s_hi, 2);

    // ---- step 3: O = A V (V via trans ldsm) ----
    float co[10][4];
#pragma unroll
    for (int j = 0; j < 10; j++)
#pragma unroll
        for (int e = 0; e < 4; e++) co[j][e] = 0.f;

#pragma unroll
    for (int ks2 = 0; ks2 < 8; ks2++) {
        uint32_t ahf[4], alf[4];
        split2(ca[ks2 * 2 + 0][0], ca[ks2 * 2 + 0][1], ahf[0], alf[0]);
        split2(ca[ks2 * 2 + 0][2], ca[ks2 * 2 + 0][3], ahf[1], alf[1]);
        split2(ca[ks2 * 2 + 1][0], ca[ks2 * 2 + 1][1], ahf[2], alf[2]);
        split2(ca[ks2 * 2 + 1][2], ca[ks2 * 2 + 1][3], ahf[3], alf[3]);
#pragma unroll
        for (int fg = 0; fg < 4; fg++) {
            uint32_t bo = (uint32_t)((ks2 * 16 + t_row) * QVP + (fg * 16 + t_col) * 2);
            uint32_t bvh[4], bvl[4];
            ldsm4t(bvh, sb + OFF_VH + bo);
            ldsm4t(bvl, sb + OFF_VL + bo);
            mma16816(co[fg * 2 + 0], ahf, &bvh[0]);
            mma16816(co[fg * 2 + 1], ahf, &bvh[2]);
            mma16816(co[fg * 2 + 0], ahf, &bvl[0]);
            mma16816(co[fg * 2 + 1], ahf, &bvl[2]);
            mma16816(co[fg * 2 + 0], alf, &bvh[0]);
            mma16816(co[fg * 2 + 1], alf, &bvh[2]);
        }
    }

    // ---- step 4: O += Q [Sp | zp] (Sp via trans ldsm; col 64 = zp) ----
#pragma unroll
    for (int ks = 0; ks < 4; ks++) {
        uint32_t aqh[4], aql[4];
        uint32_t ao = (uint32_t)((w * 16 + a_row) * QVP + (ks * 16 + a_koff) * 2);
        ldsm4(aqh, sb + OFF_QH + ao);
        ldsm4(aql, sb + OFF_QL + ao);
#pragma unroll
        for (int fg = 0; fg < 5; fg++) {
            uint32_t bo = (uint32_t)((ks * 16 + t_row) * SPB + (fg * 16 + t_col) * 2);
            uint32_t bsh[4], bsl[4];
            ldsm4t(bsh, sb + OFF_SPH + bo);
            ldsm4t(bsl, sb + OFF_SPL + bo);
            mma16816(co[fg * 2 + 0], aqh, &bsh[0]);
            mma16816(co[fg * 2 + 1], aqh, &bsh[2]);
            mma16816(co[fg * 2 + 0], aqh, &bsl[0]);
            mma16816(co[fg * 2 + 1], aqh, &bsl[2]);
            mma16816(co[fg * 2 + 0], aql, &bsh[0]);
            mma16816(co[fg * 2 + 1], aql, &bsh[2]);
        }
    }

    // ---- step 5: denominator, divide, write pre-split xo ----
    float qz_lo = __shfl_sync(0xffffffffu, co[8][0], lid & ~3);
    float qz_hi = __shfl_sync(0xffffffffu, co[8][2], lid & ~3);
    float inv_lo = 1.f / (s_lo + qz_lo + EPSF);
    float inv_hi = 1.f / (s_hi + qz_hi + EPSF);

#pragma unroll
    for (int j = 0; j < 8; j++) {
        int col = h * HS + j * 8 + tq * 2;
        size_t i_lo = (size_t)(t0g + row_lo) * D_MODEL + col;
        size_t i_hi = (size_t)(t0g + row_hi) * D_MODEL + col;
        uint32_t hw, lw;
        split2(co[j][0] * inv_lo, co[j][1] * inv_lo, hw, lw);
        *(uint32_t*)(g_ah + i_lo) = hw;
        *(uint32_t*)(g_al + i_lo) = lw;
        split2(co[j][2] * inv_hi, co[j][3] * inv_hi, hw, lw);
        *(uint32_t*)(g_ah + i_hi) = hw;
        *(uint32_t*)(g_al + i_hi) = lw;
    }
}

// ---------------- launch ----------------
extern "C" void kernel_launch(void* const* d_in, const int* in_sizes, int n_in,
                              void* d_out, int out_size) {
    const float* x     = (const float*)d_in[0];
    const float* w_qkv = (const float*)d_in[1];
    const float* w_out = (const float*)d_in[2];
    float* out = (float*)d_out;

    __nv_bfloat16 *ah, *al, *b1h, *b1l, *b2h, *b2l;
    cudaGetSymbolAddress((void**)&ah,  g_ah);
    cudaGetSymbolAddress((void**)&al,  g_al);
    cudaGetSymbolAddress((void**)&b1h, g_b1h);
    cudaGetSymbolAddress((void**)&b1l, g_b1l);
    cudaGetSymbolAddress((void**)&b2h, g_b2h);
    cudaGetSymbolAddress((void**)&b2l, g_b2l);

    const int CHUNK_SMEM = 2 * CHUNK * HS * sizeof(float);
    cudaFuncSetAttribute(gemm_bf16s<1>, cudaFuncAttributeMaxDynamicSharedMemorySize, GSM_TOTAL);
    cudaFuncSetAttribute(gemm_bf16s<0>, cudaFuncAttributeMaxDynamicSharedMemorySize, GSM_TOTAL);
    cudaFuncSetAttribute(chunk_sums, cudaFuncAttributeMaxDynamicSharedMemorySize, CHUNK_SMEM);
    cudaFuncSetAttribute(attn_mma,   cudaFuncAttributeMaxDynamicSharedMemorySize, ATTN_SMEM_B);

    splitk<<<(T_LEN * D_MODEL / 4 + 255) / 256, 256>>>(x, ah, al, T_LEN * D_MODEL / 4);
    splitk<<<(3 * D_MODEL * D_MODEL / 4 + 255) / 256, 256>>>(w_qkv, b1h, b1l, 3 * D_MODEL * D_MODEL / 4);
    splitk<<<(D_MODEL * D_MODEL / 4 + 255) / 256, 256>>>(w_out, b2h, b2l, D_MODEL * D_MODEL / 4);

    // GEMM1: fused phi + split epilogue -> g_qkv{h,l}
    dim3 g1(3 * D_MODEL / 128, T_LEN / 128);   // (24, 16)
    gemm_bf16s<1><<<g1, 128, GSM_TOTAL>>>(ah, al, b1h, b1l, nullptr, T_LEN, 3 * D_MODEL, D_MODEL);

    chunk_sums<<<H_NUM * NC, 256, CHUNK_SMEM>>>();
    chunk_prefix<<<H_NUM * 20, 256>>>();
    attn_mma<<<H_NUM * NC, 256, ATTN_SMEM_B>>>();   // writes xo pre-split into ah/al

    dim3 g2(D_MODEL / 128, T_LEN / 128);       // (8, 16)
    gemm_bf16s<0><<<g2, 128, GSM_TOTAL>>>(ah, al, b2h, b2l, out, T_LEN, D_MODEL, D_MODEL);
}

// round 6
// speedup vs baseline: 2.7512x; 1.1630x over previous
#include <cuda_runtime.h>
#include <cuda_bf16.h>
#include <cstdint>

#define T_LEN 2048
#define D_MODEL 1024
#define H_NUM 16
#define HS 64
#define CHUNK 128
#define NC 16
#define EPSF 1e-6f
#define SCP 80   /* Sc/Sp col count: 64 data + zc/zp at col 64 + 15 zero */

// ---------------- scratch (static device globals) ----------------
__device__ float g_Sc [H_NUM * NC * HS * SCP];
__device__ __align__(16) __nv_bfloat16 g_sph[H_NUM * NC * HS * SCP];
__device__ __align__(16) __nv_bfloat16 g_spl[H_NUM * NC * HS * SCP];

__device__ __align__(16) __nv_bfloat16 g_qkvh[3][H_NUM][T_LEN][HS];
__device__ __align__(16) __nv_bfloat16 g_qkvl[3][H_NUM][T_LEN][HS];

__device__ __align__(16) __nv_bfloat16 g_ah [T_LEN * D_MODEL];
__device__ __align__(16) __nv_bfloat16 g_al [T_LEN * D_MODEL];
__device__ __align__(16) __nv_bfloat16 g_b1h[3 * D_MODEL * D_MODEL];
__device__ __align__(16) __nv_bfloat16 g_b1l[3 * D_MODEL * D_MODEL];
__device__ __align__(16) __nv_bfloat16 g_b2h[D_MODEL * D_MODEL];
__device__ __align__(16) __nv_bfloat16 g_b2l[D_MODEL * D_MODEL];

__device__ __forceinline__ float phi(float x) {
    return x > 0.f ? x + 1.f : expf(x);
}

// ---------------- fp32 -> bf16 (hi, lo) ----------------
__device__ __forceinline__ void split1(float x, __nv_bfloat16& h, __nv_bfloat16& l) {
    h = __float2bfloat16_rn(x);
    l = __float2bfloat16_rn(x - __bfloat162float(h));
}
__device__ __forceinline__ void split2(float a, float b, uint32_t& hi, uint32_t& lo) {
    __nv_bfloat16 ha, la, hb, lb;
    split1(a, ha, la);
    split1(b, hb, lb);
    hi = (uint32_t)__bfloat16_as_ushort(ha) | ((uint32_t)__bfloat16_as_ushort(hb) << 16);
    lo = (uint32_t)__bfloat16_as_ushort(la) | ((uint32_t)__bfloat16_as_ushort(lb) << 16);
}

__global__ __launch_bounds__(256) void splitk(const float* __restrict__ s,
                                              __nv_bfloat16* __restrict__ h,
                                              __nv_bfloat16* __restrict__ l,
                                              int n4) {
    int i = blockIdx.x * 256 + threadIdx.x;
    if (i >= n4) return;
    float4 v = ((const float4*)s)[i];
    uint32_t h01, l01, h23, l23;
    split2(v.x, v.y, h01, l01);
    split2(v.z, v.w, h23, l23);
    ((uint2*)h)[i] = make_uint2(h01, h23);
    ((uint2*)l)[i] = make_uint2(l01, l23);
}

// ---------------- mma helpers ----------------
__device__ __forceinline__ uint32_t smem_u32(const void* p) {
    uint32_t a;
    asm("{ .reg .u64 t; cvta.to.shared.u64 t, %1; cvt.u32.u64 %0, t; }" : "=r"(a) : "l"(p));
    return a;
}
__device__ __forceinline__ void ldsm4(uint32_t* r, uint32_t addr) {
    asm volatile("ldmatrix.sync.aligned.m8n8.x4.shared.b16 {%0,%1,%2,%3}, [%4];"
                 : "=r"(r[0]), "=r"(r[1]), "=r"(r[2]), "=r"(r[3]) : "r"(addr));
}
__device__ __forceinline__ void ldsm4t(uint32_t* r, uint32_t addr) {
    asm volatile("ldmatrix.sync.aligned.m8n8.x4.trans.shared.b16 {%0,%1,%2,%3}, [%4];"
                 : "=r"(r[0]), "=r"(r[1]), "=r"(r[2]), "=r"(r[3]) : "r"(addr));
}
__device__ __forceinline__ void mma16816(float* d, const uint32_t* a, const uint32_t* b) {
    asm volatile("mma.sync.aligned.m16n8k16.row.col.f32.bf16.bf16.f32 "
                 "{%0,%1,%2,%3},{%4,%5,%6,%7},{%8,%9},{%0,%1,%2,%3};"
                 : "+f"(d[0]), "+f"(d[1]), "+f"(d[2]), "+f"(d[3])
                 : "r"(a[0]), "r"(a[1]), "r"(a[2]), "r"(a[3]), "r"(b[0]), "r"(b[1]));
}
#define CP16(dst, src) \
    asm volatile("cp.async.cg.shared.global [%0], [%1], 16;" :: "r"(dst), "l"(src) : "memory")
#define CP_COMMIT() asm volatile("cp.async.commit_group;" ::: "memory")
#define CP_WAIT0()  asm volatile("cp.async.wait_group 0;" ::: "memory")

// ============================================================================
// split-bf16 GEMM: C = A[M][K] @ B[N][K]^T. CTA 128x128, 8 warps of 32x64,
// BK=32, double buffer, 2 CTA/SM. Product-major mma ordering (RAW dist = 16).
// ============================================================================
#define TPITCH 80                        /* 32 bf16 + 16B pad */
#define TILE_B (128 * TPITCH)            /* 10240 */
#define STAGE_B (4 * TILE_B)             /* 40960 */
#define GSM_TOTAL (2 * STAGE_B)          /* 81920 */

template<int EPI>
__global__ __launch_bounds__(256, 2) void gemm_bf16s(
        const __nv_bfloat16* __restrict__ Ah, const __nv_bfloat16* __restrict__ Al,
        const __nv_bfloat16* __restrict__ Bh, const __nv_bfloat16* __restrict__ Bl,
        float* __restrict__ C, int M, int N, int K) {
    extern __shared__ char smem[];
    const uint32_t sb = smem_u32(smem);

    const int tid = threadIdx.x;
    const int wid = tid >> 5, lid = tid & 31;
    const int warp_m = wid & 3, warp_n = wid >> 2;
    const int m0 = blockIdx.y * 128, n0 = blockIdx.x * 128;
    const int NKB = K >> 5;

    const __nv_bfloat16* srcs[4] = {Ah, Al, Bh, Bl};

    const int a_row  = lid & 15;
    const int a_koff = (lid >> 4) * 8;
    const int b_n    = (lid & 7) + ((lid >> 4) << 3);
    const int b_ko   = ((lid >> 3) & 1) * 8;
    const int g = lid >> 2, tg = lid & 3;

    float acc[2][8][4];
#pragma unroll
    for (int i = 0; i < 2; i++)
#pragma unroll
        for (int j = 0; j < 8; j++)
#pragma unroll
            for (int k = 0; k < 4; k++) acc[i][j][k] = 0.f;

    // prologue: stage 0 (2048 chunks of 16B, 8 per thread)
#pragma unroll
    for (int j = 0; j < 8; j++) {
        int chunkid = tid + j * 256;
        int tile = chunkid >> 9;
        int within = chunkid & 511;
        int row = within >> 2, c = within & 3;
        int grow = (tile < 2 ? m0 : n0) + row;
        CP16(sb + tile * TILE_B + row * TPITCH + c * 16,
             srcs[tile] + (size_t)grow * K + c * 8);
    }
    CP_COMMIT();
    CP_WAIT0();
    __syncthreads();

#pragma unroll 1
    for (int kb = 0; kb < NKB; kb++) {
        const int s = kb & 1;
        const uint32_t stage = sb + s * STAGE_B;

        if (kb + 1 < NKB) {
            const uint32_t nstage = sb + (1 - s) * STAGE_B;
#pragma unroll
            for (int j = 0; j < 8; j++) {
                int chunkid = tid + j * 256;
                int tile = chunkid >> 9;
                int within = chunkid & 511;
                int row = within >> 2, c = within & 3;
                int grow = (tile < 2 ? m0 : n0) + row;
                CP16(nstage + tile * TILE_B + row * TPITCH + c * 16,
                     srcs[tile] + (size_t)grow * K + (kb + 1) * 32 + c * 8);
            }
            CP_COMMIT();
        }

        const uint32_t tAh = stage;
        const uint32_t tAl = stage + TILE_B;
        const uint32_t tBh = stage + 2 * TILE_B;
        const uint32_t tBl = stage + 3 * TILE_B;

#pragma unroll
        for (int ks = 0; ks < 2; ks++) {
            uint32_t a_h[2][4], a_l[2][4];
#pragma unroll
            for (int mt = 0; mt < 2; mt++) {
                uint32_t ao = (uint32_t)((warp_m * 32 + mt * 16 + a_row) * TPITCH +
                                         (ks * 16 + a_koff) * 2);
                ldsm4(a_h[mt], tAh + ao);
                ldsm4(a_l[mt], tAl + ao);
            }
            uint32_t bf[4][4];
#pragma unroll
            for (int ng = 0; ng < 4; ng++) {
                uint32_t bo = (uint32_t)((warp_n * 64 + ng * 16 + b_n) * TPITCH +
                                         (ks * 16 + b_ko) * 2);
                ldsm4(bf[ng], tBh + bo);
            }
            // product hh: 16 mmas, distinct accs
#pragma unroll
            for (int ng = 0; ng < 4; ng++)
#pragma unroll
                for (int mt = 0; mt < 2; mt++) {
                    mma16816(acc[mt][ng * 2 + 0], a_h[mt], &bf[ng][0]);
                    mma16816(acc[mt][ng * 2 + 1], a_h[mt], &bf[ng][2]);
                }
            // product lh (reuse bh regs)
#pragma unroll
            for (int ng = 0; ng < 4; ng++)
#pragma unroll
                for (int mt = 0; mt < 2; mt++) {
                    mma16816(acc[mt][ng * 2 + 0], a_l[mt], &bf[ng][0]);
                    mma16816(acc[mt][ng * 2 + 1], a_l[mt], &bf[ng][2]);
                }
            // reload b with lo tiles
#pragma unroll
            for (int ng = 0; ng < 4; ng++) {
                uint32_t bo = (uint32_t)((warp_n * 64 + ng * 16 + b_n) * TPITCH +
                                         (ks * 16 + b_ko) * 2);
                ldsm4(bf[ng], tBl + bo);
            }
            // product hl
#pragma unroll
            for (int ng = 0; ng < 4; ng++)
#pragma unroll
                for (int mt = 0; mt < 2; mt++) {
                    mma16816(acc[mt][ng * 2 + 0], a_h[mt], &bf[ng][0]);
                    mma16816(acc[mt][ng * 2 + 1], a_h[mt], &bf[ng][2]);
                }
        }

        if (kb + 1 < NKB) CP_WAIT0();
        __syncthreads();
    }

    // ---- epilogue ----
    if (EPI) {
#pragma unroll
        for (int mt = 0; mt < 2; mt++) {
#pragma unroll
            for (int j = 0; j < 8; j++) {
                float* d = acc[mt][j];
                int n = n0 + warp_n * 64 + j * 8 + tg * 2;
                int sq = n >> 10, hh2 = (n >> 6) & 15, dd = n & 63;
                int r0 = m0 + warp_m * 32 + mt * 16 + g;
                float v0 = d[0], v1 = d[1], v2 = d[2], v3 = d[3];
                if (sq < 2) { v0 = phi(v0); v1 = phi(v1); v2 = phi(v2); v3 = phi(v3); }
                uint32_t hw, lw;
                split2(v0, v1, hw, lw);
                *(uint32_t*)&g_qkvh[sq][hh2][r0][dd] = hw;
                *(uint32_t*)&g_qkvl[sq][hh2][r0][dd] = lw;
                split2(v2, v3, hw, lw);
                *(uint32_t*)&g_qkvh[sq][hh2][r0 + 8][dd] = hw;
                *(uint32_t*)&g_qkvl[sq][hh2][r0 + 8][dd] = lw;
            }
        }
    } else {
#pragma unroll
        for (int mt = 0; mt < 2; mt++) {
#pragma unroll
            for (int j = 0; j < 8; j++) {
                float* d = acc[mt][j];
                int r0 = m0 + warp_m * 32 + mt * 16 + g;
                int col = n0 + warp_n * 64 + j * 8 + tg * 2;
                *(float2*)(C + (size_t)r0 * N + col)       = make_float2(d[0], d[1]);
                *(float2*)(C + (size_t)(r0 + 8) * N + col) = make_float2(d[2], d[3]);
            }
        }
    }
}

// ---------------- per-chunk KV sums: Sc[d][f] = sum_t K[t][d] V[t][f]; col 64 = zc ----
__global__ __launch_bounds__(256) void chunk_sums() {
    extern __shared__ float sm[];
    float* Ks = sm;
    float* Vs = sm + CHUNK * HS;
    int blk = blockIdx.x;
    int h = blk >> 4, cc = blk & 15;
    int t0 = cc * CHUNK;
    int tid = threadIdx.x;

    for (int i = tid; i < CHUNK * HS; i += 256) {
        int t = i >> 6, d = i & 63;
        Ks[i] = __bfloat162float(g_qkvh[1][h][t0 + t][d]) +
                __bfloat162float(g_qkvl[1][h][t0 + t][d]);
        Vs[i] = __bfloat162float(g_qkvh[2][h][t0 + t][d]) +
                __bfloat162float(g_qkvl[2][h][t0 + t][d]);
    }
    __syncthreads();

    int d0 = (tid >> 4) * 4, f0 = (tid & 15) * 4;
    float acc[4][4];
#pragma unroll
    for (int i = 0; i < 4; i++)
#pragma unroll
        for (int j = 0; j < 4; j++) acc[i][j] = 0.f;

    for (int t = 0; t < CHUNK; t++) {
        float4 k4 = *(const float4*)&Ks[t * HS + d0];
        float4 v4 = *(const float4*)&Vs[t * HS + f0];
        float kf[4] = {k4.x, k4.y, k4.z, k4.w};
        float vf[4] = {v4.x, v4.y, v4.z, v4.w};
#pragma unroll
        for (int i = 0; i < 4; i++)
#pragma unroll
            for (int j = 0; j < 4; j++)
                acc[i][j] = fmaf(kf[i], vf[j], acc[i][j]);
    }
    float* Sout = g_Sc + (size_t)blk * HS * SCP;
#pragma unroll
    for (int i = 0; i < 4; i++)
#pragma unroll
        for (int j = 0; j < 4; j++)
            Sout[(d0 + i) * SCP + f0 + j] = acc[i][j];

    if (tid < HS) {
        float z = 0.f;
        for (int t = 0; t < CHUNK; t++) z += Ks[t * HS + tid];
        Sout[tid * SCP + 64] = z;
    }
    for (int i = tid; i < HS * 15; i += 256) {
        int r = i / 15, c2 = 65 + i % 15;
        Sout[r * SCP + c2] = 0.f;
    }
}

// ---------------- exclusive prefix over chunks -> split bf16 Sp ----------------
__global__ __launch_bounds__(256) void chunk_prefix() {
    int h = blockIdx.x / 20;
    int e = (blockIdx.x % 20) * 256 + threadIdx.x;
    float run = 0.f;
#pragma unroll
    for (int c = 0; c < NC; c++) {
        size_t idx = (size_t)(h * NC + c) * (HS * SCP) + e;
        __nv_bfloat16 hh, ll;
        split1(run, hh, ll);
        g_sph[idx] = hh;
        g_spl[idx] = ll;
        run += g_Sc[idx];
    }
}

// ============================================================================
// attention per chunk (same as R5)
// ============================================================================
#define QVP 144
#define SPB 176
#define OFF_QH 0
#define OFF_QL (1 * 128 * QVP)
#define OFF_KH (2 * 128 * QVP)
#define OFF_KL (3 * 128 * QVP)
#define OFF_VH (4 * 128 * QVP)
#define OFF_VL (5 * 128 * QVP)
#define OFF_SPH (6 * 128 * QVP)
#define OFF_SPL (OFF_SPH + 64 * SPB)
#define ATTN_SMEM_B (OFF_SPL + 64 * SPB)

__global__ __launch_bounds__(256) void attn_mma() {
    extern __shared__ char smc[];
    const uint32_t sb = smem_u32(smc);

    const int blk = blockIdx.x;
    const int h = blk >> 4, cc = blk & 15;
    const int t0g = cc * CHUNK;
    const int tid = threadIdx.x;
    const int w = tid >> 5, lid = tid & 31;

#pragma unroll
    for (int j = 0; j < 24; j++) {
        int chunkid = tid + j * 256;
        int buf = chunkid >> 10;
        int within = chunkid & 1023;
        int row = within >> 3, c = within & 7;
        int sidx = buf >> 1;
        const __nv_bfloat16* srcp = (buf & 1) ? &g_qkvl[sidx][h][t0g + row][0]
                                              : &g_qkvh[sidx][h][t0g + row][0];
        CP16(sb + buf * (128 * QVP) + row * QVP + c * 16, srcp + c * 8);
    }
#pragma unroll
    for (int j = 0; j < 5; j++) {
        int chunkid = tid + j * 256;
        int buf = chunkid / 640;
        int within = chunkid % 640;
        int row = within / 10, c = within % 10;
        const __nv_bfloat16* srcp = (buf ? g_spl : g_sph) + (size_t)blk * (HS * SCP) + row * SCP + c * 8;
        CP16(sb + OFF_SPH + buf * (64 * SPB) + row * SPB + c * 16, srcp);
    }
    CP_COMMIT();
    CP_WAIT0();
    __syncthreads();

    const int a_row  = lid & 15;
    const int a_koff = (lid >> 4) * 8;
    const int b_n    = (lid & 7) + ((lid >> 4) << 3);
    const int b_ko   = ((lid >> 3) & 1) * 8;
    const int t_row  = lid & 15;
    const int t_col  = ((lid >> 4) << 3);
    const int g = lid >> 2, tq = lid & 3;

    // ---- step 1: A = Q K^T ----
    float ca[16][4];
#pragma unroll
    for (int j = 0; j < 16; j++)
#pragma unroll
        for (int e = 0; e < 4; e++) ca[j][e] = 0.f;

#pragma unroll
    for (int ks = 0; ks < 4; ks++) {
        uint32_t aqh[4], aql[4];
        uint32_t ao = (uint32_t)((w * 16 + a_row) * QVP + (ks * 16 + a_koff) * 2);
        ldsm4(aqh, sb + OFF_QH + ao);
        ldsm4(aql, sb + OFF_QL + ao);
#pragma unroll
        for (int sg = 0; sg < 8; sg++) {
            uint32_t bo = (uint32_t)((sg * 16 + b_n) * QVP + (ks * 16 + b_ko) * 2);
            uint32_t bkh[4], bkl[4];
            ldsm4(bkh, sb + OFF_KH + bo);
            ldsm4(bkl, sb + OFF_KL + bo);
            mma16816(ca[sg * 2 + 0], aqh, &bkh[0]);
            mma16816(ca[sg * 2 + 1], aqh, &bkh[2]);
            mma16816(ca[sg * 2 + 0], aqh, &bkl[0]);
            mma16816(ca[sg * 2 + 1], aqh, &bkl[2]);
            mma16816(ca[sg * 2 + 0], aql, &bkh[0]);
            mma16816(ca[sg * 2 + 1], aql, &bkh[2]);
        }
    }

    // ---- step 2: causal mask + rowsum ----
    const int row_lo = w * 16 + g, row_hi = row_lo + 8;
    float s_lo = 0.f, s_hi = 0.f;
#pragma unroll
    for (int j = 0; j < 16; j++) {
        int c0 = j * 8 + tq * 2;
        if (c0     > row_lo) ca[j][0] = 0.f;
        if (c0 + 1 > row_lo) ca[j][1] = 0.f;
        if (c0     > row_hi) ca[j][2] = 0.f;
        if (c0 + 1 > row_hi) ca[j][3] = 0.f;
        s_lo += ca[j][0] + ca[j][1];
        s_hi += ca[j][2] + ca[j][3];
    }
    s_lo += __shfl_xor_sync(0xffffffffu, s_lo, 1);
    s_lo += __shfl_xor_sync(0xffffffffu, s_lo, 2);
    s_hi += __shfl_xor_sync(0xffffffffu, s_hi, 1);
    s_hi += __shfl_xor_sync(0xffffffffu, s_hi, 2);

    // ---- step 3: O = A V ----
    float co[10][4];
#pragma unroll
    for (int j = 0; j < 10; j++)
#pragma unroll
        for (int e = 0; e < 4; e++) co[j][e] = 0.f;

#pragma unroll
    for (int ks2 = 0; ks2 < 8; ks2++) {
        uint32_t ahf[4], alf[4];
        split2(ca[ks2 * 2 + 0][0], ca[ks2 * 2 + 0][1], ahf[0], alf[0]);
        split2(ca[ks2 * 2 + 0][2], ca[ks2 * 2 + 0][3], ahf[1], alf[1]);
        split2(ca[ks2 * 2 + 1][0], ca[ks2 * 2 + 1][1], ahf[2], alf[2]);
        split2(ca[ks2 * 2 + 1][2], ca[ks2 * 2 + 1][3], ahf[3], alf[3]);
#pragma unroll
        for (int fg = 0; fg < 4; fg++) {
            uint32_t bo = (uint32_t)((ks2 * 16 + t_row) * QVP + (fg * 16 + t_col) * 2);
            uint32_t bvh[4], bvl[4];
            ldsm4t(bvh, sb + OFF_VH + bo);
            ldsm4t(bvl, sb + OFF_VL + bo);
            mma16816(co[fg * 2 + 0], ahf, &bvh[0]);
            mma16816(co[fg * 2 + 1], ahf, &bvh[2]);
            mma16816(co[fg * 2 + 0], ahf, &bvl[0]);
            mma16816(co[fg * 2 + 1], ahf, &bvl[2]);
            mma16816(co[fg * 2 + 0], alf, &bvh[0]);
            mma16816(co[fg * 2 + 1], alf, &bvh[2]);
        }
    }

    // ---- step 4: O += Q [Sp | zp] ----
#pragma unroll
    for (int ks = 0; ks < 4; ks++) {
        uint32_t aqh[4], aql[4];
        uint32_t ao = (uint32_t)((w * 16 + a_row) * QVP + (ks * 16 + a_koff) * 2);
        ldsm4(aqh, sb + OFF_QH + ao);
        ldsm4(aql, sb + OFF_QL + ao);
#pragma unroll
        for (int fg = 0; fg < 5; fg++) {
            uint32_t bo = (uint32_t)((ks * 16 + t_row) * SPB + (fg * 16 + t_col) * 2);
            uint32_t bsh[4], bsl[4];
            ldsm4t(bsh, sb + OFF_SPH + bo);
            ldsm4t(bsl, sb + OFF_SPL + bo);
            mma16816(co[fg * 2 + 0], aqh, &bsh[0]);
            mma16816(co[fg * 2 + 1], aqh, &bsh[2]);
            mma16816(co[fg * 2 + 0], aqh, &bsl[0]);
            mma16816(co[fg * 2 + 1], aqh, &bsl[2]);
            mma16816(co[fg * 2 + 0], aql, &bsh[0]);
            mma16816(co[fg * 2 + 1], aql, &bsh[2]);
        }
    }

    // ---- step 5: denominator, divide, write pre-split xo ----
    float qz_lo = __shfl_sync(0xffffffffu, co[8][0], lid & ~3);
    float qz_hi = __shfl_sync(0xffffffffu, co[8][2], lid & ~3);
    float inv_lo = 1.f / (s_lo + qz_lo + EPSF);
    float inv_hi = 1.f / (s_hi + qz_hi + EPSF);

#pragma unroll
    for (int j = 0; j < 8; j++) {
        int col = h * HS + j * 8 + tq * 2;
        size_t i_lo = (size_t)(t0g + row_lo) * D_MODEL + col;
        size_t i_hi = (size_t)(t0g + row_hi) * D_MODEL + col;
        uint32_t hw, lw;
        split2(co[j][0] * inv_lo, co[j][1] * inv_lo, hw, lw);
        *(uint32_t*)(g_ah + i_lo) = hw;
        *(uint32_t*)(g_al + i_lo) = lw;
        split2(co[j][2] * inv_hi, co[j][3] * inv_hi, hw, lw);
        *(uint32_t*)(g_ah + i_hi) = hw;
        *(uint32_t*)(g_al + i_hi) = lw;
    }
}

// ---------------- launch ----------------
extern "C" void kernel_launch(void* const* d_in, const int* in_sizes, int n_in,
                              void* d_out, int out_size) {
    const float* x     = (const float*)d_in[0];
    const float* w_qkv = (const float*)d_in[1];
    const float* w_out = (const float*)d_in[2];
    float* out = (float*)d_out;

    __nv_bfloat16 *ah, *al, *b1h, *b1l, *b2h, *b2l;
    cudaGetSymbolAddress((void**)&ah,  g_ah);
    cudaGetSymbolAddress((void**)&al,  g_al);
    cudaGetSymbolAddress((void**)&b1h, g_b1h);
    cudaGetSymbolAddress((void**)&b1l, g_b1l);
    cudaGetSymbolAddress((void**)&b2h, g_b2h);
    cudaGetSymbolAddress((void**)&b2l, g_b2l);

    const int CHUNK_SMEM = 2 * CHUNK * HS * sizeof(float);
    cudaFuncSetAttribute(gemm_bf16s<1>, cudaFuncAttributeMaxDynamicSharedMemorySize, GSM_TOTAL);
    cudaFuncSetAttribute(gemm_bf16s<0>, cudaFuncAttributeMaxDynamicSharedMemorySize, GSM_TOTAL);
    cudaFuncSetAttribute(chunk_sums, cudaFuncAttributeMaxDynamicSharedMemorySize, CHUNK_SMEM);
    cudaFuncSetAttribute(attn_mma,   cudaFuncAttributeMaxDynamicSharedMemorySize, ATTN_SMEM_B);

    splitk<<<(T_LEN * D_MODEL / 4 + 255) / 256, 256>>>(x, ah, al, T_LEN * D_MODEL / 4);
    splitk<<<(3 * D_MODEL * D_MODEL / 4 + 255) / 256, 256>>>(w_qkv, b1h, b1l, 3 * D_MODEL * D_MODEL / 4);
    splitk<<<(D_MODEL * D_MODEL / 4 + 255) / 256, 256>>>(w_out, b2h, b2l, D_MODEL * D_MODEL / 4);

    dim3 g1(3 * D_MODEL / 128, T_LEN / 128);   // (24, 16)
    gemm_bf16s<1><<<g1, 256, GSM_TOTAL>>>(ah, al, b1h, b1l, nullptr, T_LEN, 3 * D_MODEL, D_MODEL);

    chunk_sums<<<H_NUM * NC, 256, CHUNK_SMEM>>>();
    chunk_prefix<<<H_NUM * 20, 256>>>();
    attn_mma<<<H_NUM * NC, 256, ATTN_SMEM_B>>>();

    dim3 g2(D_MODEL / 128, T_LEN / 128);       // (8, 16)
    gemm_bf16s<0><<<g2, 256, GSM_TOTAL>>>(ah, al, b2h, b2l, out, T_LEN, D_MODEL, D_MODEL);
}

// round 7
// speedup vs baseline: 2.7516x; 1.0001x over previous
#include <cuda_runtime.h>
#include <cuda_bf16.h>
#include <cstdint>

#define T_LEN 2048
#define D_MODEL 1024
#define H_NUM 16
#define HS 64
#define CHUNK 128
#define NC 16
#define EPSF 1e-6f
#define SCP 80   /* Sc/Sp col count: 64 data + zc/zp at col 64 + 15 zero */

// ---------------- scratch (static device globals) ----------------
__device__ float g_Sc [H_NUM * NC * HS * SCP];
__device__ __align__(16) __nv_bfloat16 g_sph[H_NUM * NC * HS * SCP];
__device__ __align__(16) __nv_bfloat16 g_spl[H_NUM * NC * HS * SCP];

__device__ __align__(16) __nv_bfloat16 g_qkvh[3][H_NUM][T_LEN][HS];
__device__ __align__(16) __nv_bfloat16 g_qkvl[3][H_NUM][T_LEN][HS];

__device__ __align__(16) __nv_bfloat16 g_ah [T_LEN * D_MODEL];
__device__ __align__(16) __nv_bfloat16 g_al [T_LEN * D_MODEL];
__device__ __align__(16) __nv_bfloat16 g_b1h[3 * D_MODEL * D_MODEL];
__device__ __align__(16) __nv_bfloat16 g_b1l[3 * D_MODEL * D_MODEL];
__device__ __align__(16) __nv_bfloat16 g_b2h[D_MODEL * D_MODEL];
__device__ __align__(16) __nv_bfloat16 g_b2l[D_MODEL * D_MODEL];

__device__ __forceinline__ float phi(float x) {
    return x > 0.f ? x + 1.f : expf(x);
}

// ---------------- fp32 -> bf16 (hi, lo) ----------------
__device__ __forceinline__ void split1(float x, __nv_bfloat16& h, __nv_bfloat16& l) {
    h = __float2bfloat16_rn(x);
    l = __float2bfloat16_rn(x - __bfloat162float(h));
}
__device__ __forceinline__ void split2(float a, float b, uint32_t& hi, uint32_t& lo) {
    __nv_bfloat16 ha, la, hb, lb;
    split1(a, ha, la);
    split1(b, hb, lb);
    hi = (uint32_t)__bfloat16_as_ushort(ha) | ((uint32_t)__bfloat16_as_ushort(hb) << 16);
    lo = (uint32_t)__bfloat16_as_ushort(la) | ((uint32_t)__bfloat16_as_ushort(lb) << 16);
}

__global__ __launch_bounds__(256) void splitk(const float* __restrict__ s,
                                              __nv_bfloat16* __restrict__ h,
                                              __nv_bfloat16* __restrict__ l,
                                              int n4) {
    int i = blockIdx.x * 256 + threadIdx.x;
    if (i >= n4) return;
    float4 v = ((const float4*)s)[i];
    uint32_t h01, l01, h23, l23;
    split2(v.x, v.y, h01, l01);
    split2(v.z, v.w, h23, l23);
    ((uint2*)h)[i] = make_uint2(h01, h23);
    ((uint2*)l)[i] = make_uint2(l01, l23);
}

// ---------------- mma helpers ----------------
__device__ __forceinline__ uint32_t smem_u32(const void* p) {
    uint32_t a;
    asm("{ .reg .u64 t; cvta.to.shared.u64 t, %1; cvt.u32.u64 %0, t; }" : "=r"(a) : "l"(p));
    return a;
}
__device__ __forceinline__ void ldsm4(uint32_t* r, uint32_t addr) {
    asm volatile("ldmatrix.sync.aligned.m8n8.x4.shared.b16 {%0,%1,%2,%3}, [%4];"
                 : "=r"(r[0]), "=r"(r[1]), "=r"(r[2]), "=r"(r[3]) : "r"(addr));
}
__device__ __forceinline__ void ldsm4t(uint32_t* r, uint32_t addr) {
    asm volatile("ldmatrix.sync.aligned.m8n8.x4.trans.shared.b16 {%0,%1,%2,%3}, [%4];"
                 : "=r"(r[0]), "=r"(r[1]), "=r"(r[2]), "=r"(r[3]) : "r"(addr));
}
__device__ __forceinline__ void mma16816(float* d, const uint32_t* a, const uint32_t* b) {
    asm volatile("mma.sync.aligned.m16n8k16.row.col.f32.bf16.bf16.f32 "
                 "{%0,%1,%2,%3},{%4,%5,%6,%7},{%8,%9},{%0,%1,%2,%3};"
                 : "+f"(d[0]), "+f"(d[1]), "+f"(d[2]), "+f"(d[3])
                 : "r"(a[0]), "r"(a[1]), "r"(a[2]), "r"(a[3]), "r"(b[0]), "r"(b[1]));
}
#define CP16(dst, src) \
    asm volatile("cp.async.cg.shared.global [%0], [%1], 16;" :: "r"(dst), "l"(src) : "memory")
#define CP_COMMIT() asm volatile("cp.async.commit_group;" ::: "memory")
#define CP_WAIT0()  asm volatile("cp.async.wait_group 0;" ::: "memory")

// ============================================================================
// split-bf16 GEMM: C = A[M][K] @ B[N][K]^T. CTA 128x128, 8 warps of 32x64,
// BK=32, double buffer, 2 CTA/SM. Product-major mma ordering (RAW dist = 16).
// ============================================================================
#define TPITCH 80                        /* 32 bf16 + 16B pad */
#define TILE_B (128 * TPITCH)            /* 10240 */
#define STAGE_B (4 * TILE_B)             /* 40960 */
#define GSM_TOTAL (2 * STAGE_B)          /* 81920 */

template<int EPI>
__global__ __launch_bounds__(256, 2) void gemm_bf16s(
        const __nv_bfloat16* __restrict__ Ah, const __nv_bfloat16* __restrict__ Al,
        const __nv_bfloat16* __restrict__ Bh, const __nv_bfloat16* __restrict__ Bl,
        float* __restrict__ C, int M, int N, int K) {
    extern __shared__ char smem[];
    const uint32_t sb = smem_u32(smem);

    const int tid = threadIdx.x;
    const int wid = tid >> 5, lid = tid & 31;
    const int warp_m = wid & 3, warp_n = wid >> 2;
    const int m0 = blockIdx.y * 128, n0 = blockIdx.x * 128;
    const int NKB = K >> 5;

    const __nv_bfloat16* srcs[4] = {Ah, Al, Bh, Bl};

    const int a_row  = lid & 15;
    const int a_koff = (lid >> 4) * 8;
    const int b_n    = (lid & 7) + ((lid >> 4) << 3);
    const int b_ko   = ((lid >> 3) & 1) * 8;
    const int g = lid >> 2, tg = lid & 3;

    float acc[2][8][4];
#pragma unroll
    for (int i = 0; i < 2; i++)
#pragma unroll
        for (int j = 0; j < 8; j++)
#pragma unroll
            for (int k = 0; k < 4; k++) acc[i][j][k] = 0.f;

    // prologue: stage 0 (2048 chunks of 16B, 8 per thread)
#pragma unroll
    for (int j = 0; j < 8; j++) {
        int chunkid = tid + j * 256;
        int tile = chunkid >> 9;
        int within = chunkid & 511;
        int row = within >> 2, c = within & 3;
        int grow = (tile < 2 ? m0 : n0) + row;
        CP16(sb + tile * TILE_B + row * TPITCH + c * 16,
             srcs[tile] + (size_t)grow * K + c * 8);
    }
    CP_COMMIT();
    CP_WAIT0();
    __syncthreads();

#pragma unroll 1
    for (int kb = 0; kb < NKB; kb++) {
        const int s = kb & 1;
        const uint32_t stage = sb + s * STAGE_B;

        if (kb + 1 < NKB) {
            const uint32_t nstage = sb + (1 - s) * STAGE_B;
#pragma unroll
            for (int j = 0; j < 8; j++) {
                int chunkid = tid + j * 256;
                int tile = chunkid >> 9;
                int within = chunkid & 511;
                int row = within >> 2, c = within & 3;
                int grow = (tile < 2 ? m0 : n0) + row;
                CP16(nstage + tile * TILE_B + row * TPITCH + c * 16,
                     srcs[tile] + (size_t)grow * K + (kb + 1) * 32 + c * 8);
            }
            CP_COMMIT();
        }

        const uint32_t tAh = stage;
        const uint32_t tAl = stage + TILE_B;
        const uint32_t tBh = stage + 2 * TILE_B;
        const uint32_t tBl = stage + 3 * TILE_B;

#pragma unroll
        for (int ks = 0; ks < 2; ks++) {
            uint32_t a_h[2][4], a_l[2][4];
#pragma unroll
            for (int mt = 0; mt < 2; mt++) {
                uint32_t ao = (uint32_t)((warp_m * 32 + mt * 16 + a_row) * TPITCH +
                                         (ks * 16 + a_koff) * 2);
                ldsm4(a_h[mt], tAh + ao);
                ldsm4(a_l[mt], tAl + ao);
            }
            uint32_t bf[4][4];
#pragma unroll
            for (int ng = 0; ng < 4; ng++) {
                uint32_t bo = (uint32_t)((warp_n * 64 + ng * 16 + b_n) * TPITCH +
                                         (ks * 16 + b_ko) * 2);
                ldsm4(bf[ng], tBh + bo);
            }
            // product hh: 16 mmas, distinct accs
#pragma unroll
            for (int ng = 0; ng < 4; ng++)
#pragma unroll
                for (int mt = 0; mt < 2; mt++) {
                    mma16816(acc[mt][ng * 2 + 0], a_h[mt], &bf[ng][0]);
                    mma16816(acc[mt][ng * 2 + 1], a_h[mt], &bf[ng][2]);
                }
            // product lh (reuse bh regs)
#pragma unroll
            for (int ng = 0; ng < 4; ng++)
#pragma unroll
                for (int mt = 0; mt < 2; mt++) {
                    mma16816(acc[mt][ng * 2 + 0], a_l[mt], &bf[ng][0]);
                    mma16816(acc[mt][ng * 2 + 1], a_l[mt], &bf[ng][2]);
                }
            // reload b with lo tiles
#pragma unroll
            for (int ng = 0; ng < 4; ng++) {
                uint32_t bo = (uint32_t)((warp_n * 64 + ng * 16 + b_n) * TPITCH +
                                         (ks * 16 + b_ko) * 2);
                ldsm4(bf[ng], tBl + bo);
            }
            // product hl
#pragma unroll
            for (int ng = 0; ng < 4; ng++)
#pragma unroll
                for (int mt = 0; mt < 2; mt++) {
                    mma16816(acc[mt][ng * 2 + 0], a_h[mt], &bf[ng][0]);
                    mma16816(acc[mt][ng * 2 + 1], a_h[mt], &bf[ng][2]);
                }
        }

        if (kb + 1 < NKB) CP_WAIT0();
        __syncthreads();
    }

    // ---- epilogue ----
    if (EPI) {
#pragma unroll
        for (int mt = 0; mt < 2; mt++) {
#pragma unroll
            for (int j = 0; j < 8; j++) {
                float* d = acc[mt][j];
                int n = n0 + warp_n * 64 + j * 8 + tg * 2;
                int sq = n >> 10, hh2 = (n >> 6) & 15, dd = n & 63;
                int r0 = m0 + warp_m * 32 + mt * 16 + g;
                float v0 = d[0], v1 = d[1], v2 = d[2], v3 = d[3];
                if (sq < 2) { v0 = phi(v0); v1 = phi(v1); v2 = phi(v2); v3 = phi(v3); }
                uint32_t hw, lw;
                split2(v0, v1, hw, lw);
                *(uint32_t*)&g_qkvh[sq][hh2][r0][dd] = hw;
                *(uint32_t*)&g_qkvl[sq][hh2][r0][dd] = lw;
                split2(v2, v3, hw, lw);
                *(uint32_t*)&g_qkvh[sq][hh2][r0 + 8][dd] = hw;
                *(uint32_t*)&g_qkvl[sq][hh2][r0 + 8][dd] = lw;
            }
        }
    } else {
#pragma unroll
        for (int mt = 0; mt < 2; mt++) {
#pragma unroll
            for (int j = 0; j < 8; j++) {
                float* d = acc[mt][j];
                int r0 = m0 + warp_m * 32 + mt * 16 + g;
                int col = n0 + warp_n * 64 + j * 8 + tg * 2;
                *(float2*)(C + (size_t)r0 * N + col)       = make_float2(d[0], d[1]);
                *(float2*)(C + (size_t)(r0 + 8) * N + col) = make_float2(d[2], d[3]);
            }
        }
    }
}

// ---------------- per-chunk KV sums: Sc[d][f] = sum_t K[t][d] V[t][f]; col 64 = zc ----
__global__ __launch_bounds__(256) void chunk_sums() {
    extern __shared__ float sm[];
    float* Ks = sm;
    float* Vs = sm + CHUNK * HS;
    int blk = blockIdx.x;
    int h = blk >> 4, cc = blk & 15;
    int t0 = cc * CHUNK;
    int tid = threadIdx.x;

    for (int i = tid; i < CHUNK * HS; i += 256) {
        int t = i >> 6, d = i & 63;
        Ks[i] = __bfloat162float(g_qkvh[1][h][t0 + t][d]) +
                __bfloat162float(g_qkvl[1][h][t0 + t][d]);
        Vs[i] = __bfloat162float(g_qkvh[2][h][t0 + t][d]) +
                __bfloat162float(g_qkvl[2][h][t0 + t][d]);
    }
    __syncthreads();

    int d0 = (tid >> 4) * 4, f0 = (tid & 15) * 4;
    float acc[4][4];
#pragma unroll
    for (int i = 0; i < 4; i++)
#pragma unroll
        for (int j = 0; j < 4; j++) acc[i][j] = 0.f;

    for (int t = 0; t < CHUNK; t++) {
        float4 k4 = *(const float4*)&Ks[t * HS + d0];
        float4 v4 = *(const float4*)&Vs[t * HS + f0];
        float kf[4] = {k4.x, k4.y, k4.z, k4.w};
        float vf[4] = {v4.x, v4.y, v4.z, v4.w};
#pragma unroll
        for (int i = 0; i < 4; i++)
#pragma unroll
            for (int j = 0; j < 4; j++)
                acc[i][j] = fmaf(kf[i], vf[j], acc[i][j]);
    }
    float* Sout = g_Sc + (size_t)blk * HS * SCP;
#pragma unroll
    for (int i = 0; i < 4; i++)
#pragma unroll
        for (int j = 0; j < 4; j++)
            Sout[(d0 + i) * SCP + f0 + j] = acc[i][j];

    if (tid < HS) {
        float z = 0.f;
        for (int t = 0; t < CHUNK; t++) z += Ks[t * HS + tid];
        Sout[tid * SCP + 64] = z;
    }
    for (int i = tid; i < HS * 15; i += 256) {
        int r = i / 15, c2 = 65 + i % 15;
        Sout[r * SCP + c2] = 0.f;
    }
}

// ---------------- exclusive prefix over chunks -> split bf16 Sp ----------------
__global__ __launch_bounds__(256) void chunk_prefix() {
    int h = blockIdx.x / 20;
    int e = (blockIdx.x % 20) * 256 + threadIdx.x;
    float run = 0.f;
#pragma unroll
    for (int c = 0; c < NC; c++) {
        size_t idx = (size_t)(h * NC + c) * (HS * SCP) + e;
        __nv_bfloat16 hh, ll;
        split1(run, hh, ll);
        g_sph[idx] = hh;
        g_spl[idx] = ll;
        run += g_Sc[idx];
    }
}

// ============================================================================
// attention per chunk (same as R5)
// ============================================================================
#define QVP 144
#define SPB 176
#define OFF_QH 0
#define OFF_QL (1 * 128 * QVP)
#define OFF_KH (2 * 128 * QVP)
#define OFF_KL (3 * 128 * QVP)
#define OFF_VH (4 * 128 * QVP)
#define OFF_VL (5 * 128 * QVP)
#define OFF_SPH (6 * 128 * QVP)
#define OFF_SPL (OFF_SPH + 64 * SPB)
#define ATTN_SMEM_B (OFF_SPL + 64 * SPB)

__global__ __launch_bounds__(256) void attn_mma() {
    extern __shared__ char smc[];
    const uint32_t sb = smem_u32(smc);

    const int blk = blockIdx.x;
    const int h = blk >> 4, cc = blk & 15;
    const int t0g = cc * CHUNK;
    const int tid = threadIdx.x;
    const int w = tid >> 5, lid = tid & 31;

#pragma unroll
    for (int j = 0; j < 24; j++) {
        int chunkid = tid + j * 256;
        int buf = chunkid >> 10;
        int within = chunkid & 1023;
        int row = within >> 3, c = within & 7;
        int sidx = buf >> 1;
        const __nv_bfloat16* srcp = (buf & 1) ? &g_qkvl[sidx][h][t0g + row][0]
                                              : &g_qkvh[sidx][h][t0g + row][0];
        CP16(sb + buf * (128 * QVP) + row * QVP + c * 16, srcp + c * 8);
    }
#pragma unroll
    for (int j = 0; j < 5; j++) {
        int chunkid = tid + j * 256;
        int buf = chunkid / 640;
        int within = chunkid % 640;
        int row = within / 10, c = within % 10;
        const __nv_bfloat16* srcp = (buf ? g_spl : g_sph) + (size_t)blk * (HS * SCP) + row * SCP + c * 8;
        CP16(sb + OFF_SPH + buf * (64 * SPB) + row * SPB + c * 16, srcp);
    }
    CP_COMMIT();
    CP_WAIT0();
    __syncthreads();

    const int a_row  = lid & 15;
    const int a_koff = (lid >> 4) * 8;
    const int b_n    = (lid & 7) + ((lid >> 4) << 3);
    const int b_ko   = ((lid >> 3) & 1) * 8;
    const int t_row  = lid & 15;
    const int t_col  = ((lid >> 4) << 3);
    const int g = lid >> 2, tq = lid & 3;

    // ---- step 1: A = Q K^T ----
    float ca[16][4];
#pragma unroll
    for (int j = 0; j < 16; j++)
#pragma unroll
        for (int e = 0; e < 4; e++) ca[j][e] = 0.f;

#pragma unroll
    for (int ks = 0; ks < 4; ks++) {
        uint32_t aqh[4], aql[4];
        uint32_t ao = (uint32_t)((w * 16 + a_row) * QVP + (ks * 16 + a_koff) * 2);
        ldsm4(aqh, sb + OFF_QH + ao);
        ldsm4(aql, sb + OFF_QL + ao);
#pragma unroll
        for (int sg = 0; sg < 8; sg++) {
            uint32_t bo = (uint32_t)((sg * 16 + b_n) * QVP + (ks * 16 + b_ko) * 2);
            uint32_t bkh[4], bkl[4];
            ldsm4(bkh, sb + OFF_KH + bo);
            ldsm4(bkl, sb + OFF_KL + bo);
            mma16816(ca[sg * 2 + 0], aqh, &bkh[0]);
            mma16816(ca[sg * 2 + 1], aqh, &bkh[2]);
            mma16816(ca[sg * 2 + 0], aqh, &bkl[0]);
            mma16816(ca[sg * 2 + 1], aqh, &bkl[2]);
            mma16816(ca[sg * 2 + 0], aql, &bkh[0]);
            mma16816(ca[sg * 2 + 1], aql, &bkh[2]);
        }
    }

    // ---- step 2: causal mask + rowsum ----
    const int row_lo = w * 16 + g, row_hi = row_lo + 8;
    float s_lo = 0.f, s_hi = 0.f;
#pragma unroll
    for (int j = 0; j < 16; j++) {
        int c0 = j * 8 + tq * 2;
        if (c0     > row_lo) ca[j][0] = 0.f;
        if (c0 + 1 > row_lo) ca[j][1] = 0.f;
        if (c0     > row_hi) ca[j][2] = 0.f;
        if (c0 + 1 > row_hi) ca[j][3] = 0.f;
        s_lo += ca[j][0] + ca[j][1];
        s_hi += ca[j][2] + ca[j][3];
    }
    s_lo += __shfl_xor_sync(0xffffffffu, s_lo, 1);
    s_lo += __shfl_xor_sync(0xffffffffu, s_lo, 2);
    s_hi += __shfl_xor_sync(0xffffffffu, s_hi, 1);
    s_hi += __shfl_xor_sync(0xffffffffu, s_hi, 2);

    // ---- step 3: O = A V ----
    float co[10][4];
#pragma unroll
    for (int j = 0; j < 10; j++)
#pragma unroll
        for (int e = 0; e < 4; e++) co[j][e] = 0.f;

#pragma unroll
    for (int ks2 = 0; ks2 < 8; ks2++) {
        uint32_t ahf[4], alf[4];
        split2(ca[ks2 * 2 + 0][0], ca[ks2 * 2 + 0][1], ahf[0], alf[0]);
        split2(ca[ks2 * 2 + 0][2], ca[ks2 * 2 + 0][3], ahf[1], alf[1]);
        split2(ca[ks2 * 2 + 1][0], ca[ks2 * 2 + 1][1], ahf[2], alf[2]);
        split2(ca[ks2 * 2 + 1][2], ca[ks2 * 2 + 1][3], ahf[3], alf[3]);
#pragma unroll
        for (int fg = 0; fg < 4; fg++) {
            uint32_t bo = (uint32_t)((ks2 * 16 + t_row) * QVP + (fg * 16 + t_col) * 2);
            uint32_t bvh[4], bvl[4];
            ldsm4t(bvh, sb + OFF_VH + bo);
            ldsm4t(bvl, sb + OFF_VL + bo);
            mma16816(co[fg * 2 + 0], ahf, &bvh[0]);
            mma16816(co[fg * 2 + 1], ahf, &bvh[2]);
            mma16816(co[fg * 2 + 0], ahf, &bvl[0]);
            mma16816(co[fg * 2 + 1], ahf, &bvl[2]);
            mma16816(co[fg * 2 + 0], alf, &bvh[0]);
            mma16816(co[fg * 2 + 1], alf, &bvh[2]);
        }
    }

    // ---- step 4: O += Q [Sp | zp] ----
#pragma unroll
    for (int ks = 0; ks < 4; ks++) {
        uint32_t aqh[4], aql[4];
        uint32_t ao = (uint32_t)((w * 16 + a_row) * QVP + (ks * 16 + a_koff) * 2);
        ldsm4(aqh, sb + OFF_QH + ao);
        ldsm4(aql, sb + OFF_QL + ao);
#pragma unroll
        for (int fg = 0; fg < 5; fg++) {
            uint32_t bo = (uint32_t)((ks * 16 + t_row) * SPB + (fg * 16 + t_col) * 2);
            uint32_t bsh[4], bsl[4];
            ldsm4t(bsh, sb + OFF_SPH + bo);
            ldsm4t(bsl, sb + OFF_SPL + bo);
            mma16816(co[fg * 2 + 0], aqh, &bsh[0]);
            mma16816(co[fg * 2 + 1], aqh, &bsh[2]);
            mma16816(co[fg * 2 + 0], aqh, &bsl[0]);
            mma16816(co[fg * 2 + 1], aqh, &bsl[2]);
            mma16816(co[fg * 2 + 0], aql, &bsh[0]);
            mma16816(co[fg * 2 + 1], aql, &bsh[2]);
        }
    }

    // ---- step 5: denominator, divide, write pre-split xo ----
    float qz_lo = __shfl_sync(0xffffffffu, co[8][0], lid & ~3);
    float qz_hi = __shfl_sync(0xffffffffu, co[8][2], lid & ~3);
    float inv_lo = 1.f / (s_lo + qz_lo + EPSF);
    float inv_hi = 1.f / (s_hi + qz_hi + EPSF);

#pragma unroll
    for (int j = 0; j < 8; j++) {
        int col = h * HS + j * 8 + tq * 2;
        size_t i_lo = (size_t)(t0g + row_lo) * D_MODEL + col;
        size_t i_hi = (size_t)(t0g + row_hi) * D_MODEL + col;
        uint32_t hw, lw;
        split2(co[j][0] * inv_lo, co[j][1] * inv_lo, hw, lw);
        *(uint32_t*)(g_ah + i_lo) = hw;
        *(uint32_t*)(g_al + i_lo) = lw;
        split2(co[j][2] * inv_hi, co[j][3] * inv_hi, hw, lw);
        *(uint32_t*)(g_ah + i_hi) = hw;
        *(uint32_t*)(g_al + i_hi) = lw;
    }
}

// ---------------- launch ----------------
extern "C" void kernel_launch(void* const* d_in, const int* in_sizes, int n_in,
                              void* d_out, int out_size) {
    const float* x     = (const float*)d_in[0];
    const float* w_qkv = (const float*)d_in[1];
    const float* w_out = (const float*)d_in[2];
    float* out = (float*)d_out;

    __nv_bfloat16 *ah, *al, *b1h, *b1l, *b2h, *b2l;
    cudaGetSymbolAddress((void**)&ah,  g_ah);
    cudaGetSymbolAddress((void**)&al,  g_al);
    cudaGetSymbolAddress((void**)&b1h, g_b1h);
    cudaGetSymbolAddress((void**)&b1l, g_b1l);
    cudaGetSymbolAddress((void**)&b2h, g_b2h);
    cudaGetSymbolAddress((void**)&b2l, g_b2l);

    const int CHUNK_SMEM = 2 * CHUNK * HS * sizeof(float);
    cudaFuncSetAttribute(gemm_bf16s<1>, cudaFuncAttributeMaxDynamicSharedMemorySize, GSM_TOTAL);
    cudaFuncSetAttribute(gemm_bf16s<0>, cudaFuncAttributeMaxDynamicSharedMemorySize, GSM_TOTAL);
    cudaFuncSetAttribute(chunk_sums, cudaFuncAttributeMaxDynamicSharedMemorySize, CHUNK_SMEM);
    cudaFuncSetAttribute(attn_mma,   cudaFuncAttributeMaxDynamicSharedMemorySize, ATTN_SMEM_B);

    splitk<<<(T_LEN * D_MODEL / 4 + 255) / 256, 256>>>(x, ah, al, T_LEN * D_MODEL / 4);
    splitk<<<(3 * D_MODEL * D_MODEL / 4 + 255) / 256, 256>>>(w_qkv, b1h, b1l, 3 * D_MODEL * D_MODEL / 4);
    splitk<<<(D_MODEL * D_MODEL / 4 + 255) / 256, 256>>>(w_out, b2h, b2l, D_MODEL * D_MODEL / 4);

    dim3 g1(3 * D_MODEL / 128, T_LEN / 128);   // (24, 16)
    gemm_bf16s<1><<<g1, 256, GSM_TOTAL>>>(ah, al, b1h, b1l, nullptr, T_LEN, 3 * D_MODEL, D_MODEL);

    chunk_sums<<<H_NUM * NC, 256, CHUNK_SMEM>>>();
    chunk_prefix<<<H_NUM * 20, 256>>>();
    attn_mma<<<H_NUM * NC, 256, ATTN_SMEM_B>>>();

    dim3 g2(D_MODEL / 128, T_LEN / 128);       // (8, 16)
    gemm_bf16s<0><<<g2, 256, GSM_TOTAL>>>(ah, al, b2h, b2l, out, T_LEN, D_MODEL, D_MODEL);
}